// round 14
// baseline (speedup 1.0000x reference)
#include <cuda_runtime.h>
#include <cuda_bf16.h>
#include <math.h>
#include <stdint.h>

#define TOK 2048
#define HD  1024
#define FD  512
#define VD  32000
#define NTV (VD/128)   // 250 column tiles for V-GEMMs

// ---------------- scratch (__device__ globals) ----------------
__device__ float g_v    [TOK*FD];
__device__ float g_preo [TOK*FD];
__device__ float g_xhat [TOK*FD];
__device__ float g_rstd [TOK];
__device__ float g_do   [TOK*FD];
__device__ float g_dv   [TOK*FD];
__device__ float g_u    [TOK*FD];
__device__ float g_t    [TOK*FD];
__device__ float g_xf   [TOK*FD];
__device__ float g_logits[(size_t)TOK*VD];
__device__ float g_rowm [TOK];
__device__ float g_rowiz[TOK];
__device__ float g_part [16*FD*HD];
__device__ float g_wt1  [FD*FD];
__device__ float g_wt2  [FD*FD];
__device__ float g_csum [16*FD];
__device__ float g_pmax [TOK*NTV];
__device__ float g_psum [TOK*NTV];
__device__ float g_lablog[TOK];
__device__ __nv_bfloat16 g_Ebf [(size_t)VD*FD];
__device__ __nv_bfloat16 g_Etbf[(size_t)FD*VD];
__device__ __nv_bfloat16 g_obf [TOK*FD];
__device__ __nv_bfloat16 g_xfbf[TOK*FD];
__device__ __nv_bfloat16 g_Pbf [(size_t)TOK*VD];

__device__ __forceinline__ float to_tf32(float x){
    float y; asm("cvt.rna.tf32.f32 %0, %1;" : "=f"(y) : "f"(x)); return y;
}
__device__ __forceinline__ void cp_async16(void* sdst, const void* gsrc){
    uint32_t s = (uint32_t)__cvta_generic_to_shared(sdst);
    asm volatile("cp.async.cg.shared.global [%0], [%1], 16;" :: "r"(s), "l"(gsrc) : "memory");
}
#define LDSM4(r0, r1, r2, r3, addr) \
    asm volatile("ldmatrix.sync.aligned.m8n8.x4.shared.b16 {%0,%1,%2,%3}, [%4];" \
        : "=r"(r0), "=r"(r1), "=r"(r2), "=r"(r3) : "r"(addr))

constexpr int SSTR = 36;
constexpr int ABUF = 128 * SSTR;
constexpr int SM_SINGLE = 4 * ABUF * 4;    // tgemm2 tf32
constexpr int SM_SPLIT  = 8 * ABUF * 4;    // tgemm split
constexpr int WSTR  = 20;
constexpr int ABUFW = 128 * WSTR;
constexpr int SM_BF = 4 * ABUFW * 4;       // 40960 B

// =====================================================================
// tgemm2b: bf16 m16n8k16 GEMM, occ-2, cp.async + ldmatrix fragments.
// C = A @ B^T (f32 accum). A [M,K] bf16, B [N,K] bf16. 128x128x32 tiles.
// GRID: blockIdx.x = M tile (fast axis — A stays L2-resident),
//       blockIdx.y = N tile, blockIdx.z = split-K.
// EPI: 0 none | 1 +b1[col]
// STAT: 0 none | 1 write C + partials | 2 partials only
// =====================================================================
template<int EPI, int STAT>
__global__ void __launch_bounds__(256, 2) tgemm2b(
    const __nv_bfloat16* __restrict__ A, const __nv_bfloat16* __restrict__ B,
    float* __restrict__ C,
    int M, int N, int lda, int ldb, int ldc, int klen,
    const float* __restrict__ b1,
    float* __restrict__ pmax, float* __restrict__ psum, int ntil)
{
    extern __shared__ uint32_t smw[];
    uint32_t* sA = smw;
    uint32_t* sB = smw + 2 * ABUFW;

    const int tid  = threadIdx.x;
    const int lane = tid & 31;
    const int wid  = tid >> 5;
    const int wm   = wid & 1;
    const int wn   = wid >> 1;
    const int bm   = blockIdx.x * 128;    // m fast
    const int bn   = blockIdx.y * 128;    // n slow
    const int kbeg = blockIdx.z * klen;

    int crow[2], cc[2];
#pragma unroll
    for (int i = 0; i < 2; i++) {
        int idx = i * 256 + tid;
        crow[i] = idx >> 2;
        cc[i]   = idx & 3;
    }

    float c[4][4][4];
#pragma unroll
    for (int mi = 0; mi < 4; mi++)
#pragma unroll
        for (int ni = 0; ni < 4; ni++)
#pragma unroll
            for (int j = 0; j < 4; j++) c[mi][ni][j] = 0.f;

    auto issue = [&](int kt, int buf) {
#pragma unroll
        for (int i = 0; i < 2; i++) {
            const int kk = kbeg + kt + cc[i] * 8;
            cp_async16(sA + buf * ABUFW + crow[i] * WSTR + cc[i] * 4,
                       A + (size_t)(bm + crow[i]) * lda + kk);
            cp_async16(sB + buf * ABUFW + crow[i] * WSTR + cc[i] * 4,
                       B + (size_t)(bn + crow[i]) * ldb + kk);
        }
        asm volatile("cp.async.commit_group;" ::: "memory");
    };

    const uint32_t smem0 = (uint32_t)__cvta_generic_to_shared(smw);
    const int sub = lane >> 3, lr = lane & 7;
    const uint32_t aLane =
        smem0 + (uint32_t)(((wm * 64 + ((sub & 1) << 3) + lr) * WSTR + ((sub >> 1) << 2)) * 4);
    const uint32_t bLane =
        smem0 + (uint32_t)(2 * ABUFW * 4) +
        (uint32_t)(((wn * 32 + ((sub & 1) << 3) + lr) * WSTR + ((sub >> 1) << 2)) * 4);

    auto compute = [&](int buf) {
        const uint32_t bufOff = (uint32_t)(buf * ABUFW * 4);
#pragma unroll
        for (int ks = 0; ks < 2; ks++) {
            const uint32_t kOff = (uint32_t)(ks * 32);
            uint32_t af[4][4], bf[4][2];
#pragma unroll
            for (int mi = 0; mi < 4; mi++) {
                LDSM4(af[mi][0], af[mi][1], af[mi][2], af[mi][3],
                      aLane + bufOff + (uint32_t)(mi * 16 * WSTR * 4) + kOff);
            }
#pragma unroll
            for (int p = 0; p < 2; p++) {
                uint32_t t0, t1, t2, t3;
                LDSM4(t0, t1, t2, t3,
                      bLane + bufOff + (uint32_t)(p * 16 * WSTR * 4) + kOff);
                bf[2 * p][0]     = t0;
                bf[2 * p + 1][0] = t1;
                bf[2 * p][1]     = t2;
                bf[2 * p + 1][1] = t3;
            }
#pragma unroll
            for (int mi = 0; mi < 4; mi++)
#pragma unroll
                for (int ni = 0; ni < 4; ni++) {
                    asm volatile(
                        "mma.sync.aligned.m16n8k16.row.col.f32.bf16.bf16.f32 "
                        "{%0,%1,%2,%3}, {%4,%5,%6,%7}, {%8,%9}, {%0,%1,%2,%3};"
                        : "+f"(c[mi][ni][0]), "+f"(c[mi][ni][1]),
                          "+f"(c[mi][ni][2]), "+f"(c[mi][ni][3])
                        : "r"(af[mi][0]), "r"(af[mi][1]), "r"(af[mi][2]), "r"(af[mi][3]),
                          "r"(bf[ni][0]), "r"(bf[ni][1]));
                }
        }
    };

    issue(0, 0);
    int buf = 0;
    for (int kt = 0; kt < klen; kt += 32) {
        const bool nxt = (kt + 32) < klen;
        if (nxt) {
            issue(kt + 32, buf ^ 1);
            asm volatile("cp.async.wait_group 1;" ::: "memory");
        } else {
            asm volatile("cp.async.wait_group 0;" ::: "memory");
        }
        __syncthreads();
        compute(buf);
        __syncthreads();
        buf ^= 1;
    }

    if (EPI == 1) {
#pragma unroll
        for (int mi = 0; mi < 4; mi++)
#pragma unroll
            for (int ni = 0; ni < 4; ni++) {
                const int col = bn + wn * 32 + ni * 8 + (lane & 3) * 2;
                float bb0 = b1[col], bb1 = b1[col + 1];
                c[mi][ni][0] += bb0; c[mi][ni][1] += bb1;
                c[mi][ni][2] += bb0; c[mi][ni][3] += bb1;
            }
    }

    if (STAT != 2) {
        float* Cp = C + (size_t)blockIdx.z * M * N;
#pragma unroll
        for (int mi = 0; mi < 4; mi++) {
            const int r0 = bm + wm * 64 + mi * 16 + (lane >> 2);
#pragma unroll
            for (int ni = 0; ni < 4; ni++) {
                const int col = bn + wn * 32 + ni * 8 + (lane & 3) * 2;
#pragma unroll
                for (int h = 0; h < 2; h++) {
                    float2 o = {c[mi][ni][h * 2], c[mi][ni][h * 2 + 1]};
                    *(float2*)(Cp + (size_t)(r0 + h * 8) * ldc + col) = o;
                }
            }
        }
    }

    if (STAT) {
        float* smax = (float*)smw;
        float* ssum = (float*)smw + 512;
        __syncthreads();
#pragma unroll
        for (int mi = 0; mi < 4; mi++)
#pragma unroll
            for (int h = 0; h < 2; h++) {
                float m = -1e30f, s = 0.f;
#pragma unroll
                for (int ni = 0; ni < 4; ni++)
#pragma unroll
                    for (int j = 0; j < 2; j++) {
                        float x = c[mi][ni][h * 2 + j];
                        float mn = fmaxf(m, x);
                        s = s * __expf(m - mn) + __expf(x - mn);
                        m = mn;
                    }
#pragma unroll
                for (int o = 1; o <= 2; o <<= 1) {
                    float m2 = __shfl_xor_sync(0xffffffff, m, o);
                    float s2 = __shfl_xor_sync(0xffffffff, s, o);
                    float mo = fmaxf(m, m2);
                    s = s * __expf(m - mo) + s2 * __expf(m2 - mo);
                    m = mo;
                }
                if ((lane & 3) == 0) {
                    int rl = wm * 64 + mi * 16 + (lane >> 2) + h * 8;
                    smax[wn * 128 + rl] = m;
                    ssum[wn * 128 + rl] = s;
                }
            }
        __syncthreads();
        if (tid < 128) {
            float m = smax[tid], s = ssum[tid];
#pragma unroll
            for (int w = 1; w < 4; w++) {
                float m2 = smax[w * 128 + tid], s2 = ssum[w * 128 + tid];
                float mo = fmaxf(m, m2);
                s = s * __expf(m - mo) + s2 * __expf(m2 - mo);
                m = mo;
            }
            pmax[(size_t)(bm + tid) * ntil + blockIdx.y] = m;
            psum[(size_t)(bm + tid) * ntil + blockIdx.y] = s;
        }
    }
}

// =====================================================================
// tgemm2: occ-2 single-tf32 GEMM (K13/K14)
// =====================================================================
template<int EPI, int STAT>
__global__ void __launch_bounds__(256, 2) tgemm2(
    const float* __restrict__ A, const float* __restrict__ B, float* __restrict__ C,
    int M, int N, int lda, int ldb, int ldc, int klen,
    const float* __restrict__ b1,
    float* __restrict__ pmax, float* __restrict__ psum, int ntil)
{
    extern __shared__ float sm[];
    float* sA = sm;
    float* sB = sm + 2 * ABUF;

    const int tid  = threadIdx.x;
    const int lane = tid & 31;
    const int wid  = tid >> 5;
    const int wm   = wid & 1;
    const int wn   = wid >> 1;
    const int bm   = blockIdx.y * 128;
    const int bn   = blockIdx.x * 128;
    const int kbeg = blockIdx.z * klen;

    int lrow[4], lq[4];
#pragma unroll
    for (int i = 0; i < 4; i++) {
        int idx = i * 256 + tid;
        lrow[i] = idx >> 3;
        lq[i]   = (idx & 7) * 4;
    }

    float c[4][4][4];
#pragma unroll
    for (int mi = 0; mi < 4; mi++)
#pragma unroll
        for (int ni = 0; ni < 4; ni++)
#pragma unroll
            for (int j = 0; j < 4; j++) c[mi][ni][j] = 0.f;

    auto issue = [&](int kt, int buf) {
#pragma unroll
        for (int i = 0; i < 4; i++) {
            const int kk = kbeg + kt + lq[i];
            const int off = buf * ABUF + lrow[i] * SSTR + lq[i];
            cp_async16(sA + off, A + (size_t)(bm + lrow[i]) * lda + kk);
            cp_async16(sB + off, B + (size_t)(bn + lrow[i]) * ldb + kk);
        }
        asm volatile("cp.async.commit_group;" ::: "memory");
    };

    const int aoff = (wm * 64 + (lane >> 2)) * SSTR + (lane & 3);
    const int boff = (wn * 32 + (lane >> 2)) * SSTR + (lane & 3);

    auto compute = [&](int buf) {
#pragma unroll
        for (int ks = 0; ks < 4; ks++) {
            const int k0 = ks * 8;
            uint32_t af[4][4], bf[4][2];
#pragma unroll
            for (int mi = 0; mi < 4; mi++) {
                const float* ap = sA + buf * ABUF + aoff + mi * 16 * SSTR + k0;
                af[mi][0] = __float_as_uint(ap[0]);
                af[mi][1] = __float_as_uint(ap[8 * SSTR]);
                af[mi][2] = __float_as_uint(ap[4]);
                af[mi][3] = __float_as_uint(ap[8 * SSTR + 4]);
            }
#pragma unroll
            for (int ni = 0; ni < 4; ni++) {
                const float* bp = sB + buf * ABUF + boff + ni * 8 * SSTR + k0;
                bf[ni][0] = __float_as_uint(bp[0]);
                bf[ni][1] = __float_as_uint(bp[4]);
            }
#pragma unroll
            for (int mi = 0; mi < 4; mi++)
#pragma unroll
                for (int ni = 0; ni < 4; ni++) {
                    asm volatile(
                        "mma.sync.aligned.m16n8k8.row.col.f32.tf32.tf32.f32 "
                        "{%0,%1,%2,%3}, {%4,%5,%6,%7}, {%8,%9}, {%0,%1,%2,%3};"
                        : "+f"(c[mi][ni][0]), "+f"(c[mi][ni][1]),
                          "+f"(c[mi][ni][2]), "+f"(c[mi][ni][3])
                        : "r"(af[mi][0]), "r"(af[mi][1]), "r"(af[mi][2]), "r"(af[mi][3]),
                          "r"(bf[ni][0]), "r"(bf[ni][1]));
                }
        }
    };

    issue(0, 0);
    int buf = 0;
    for (int kt = 0; kt < klen; kt += 32) {
        const bool nxt = (kt + 32) < klen;
        if (nxt) {
            issue(kt + 32, buf ^ 1);
            asm volatile("cp.async.wait_group 1;" ::: "memory");
        } else {
            asm volatile("cp.async.wait_group 0;" ::: "memory");
        }
        __syncthreads();
        compute(buf);
        __syncthreads();
        buf ^= 1;
    }

    if (EPI == 1) {
#pragma unroll
        for (int mi = 0; mi < 4; mi++)
#pragma unroll
            for (int ni = 0; ni < 4; ni++) {
                const int col = bn + wn * 32 + ni * 8 + (lane & 3) * 2;
                float bb0 = b1[col], bb1 = b1[col + 1];
                c[mi][ni][0] += bb0; c[mi][ni][1] += bb1;
                c[mi][ni][2] += bb0; c[mi][ni][3] += bb1;
            }
    }

    if (STAT != 2) {
        float* Cp = C + (size_t)blockIdx.z * M * N;
#pragma unroll
        for (int mi = 0; mi < 4; mi++) {
            const int r0 = bm + wm * 64 + mi * 16 + (lane >> 2);
#pragma unroll
            for (int ni = 0; ni < 4; ni++) {
                const int col = bn + wn * 32 + ni * 8 + (lane & 3) * 2;
#pragma unroll
                for (int h = 0; h < 2; h++) {
                    float2 o = {c[mi][ni][h * 2], c[mi][ni][h * 2 + 1]};
                    *(float2*)(Cp + (size_t)(r0 + h * 8) * ldc + col) = o;
                }
            }
        }
    }
}

// =====================================================================
// 3xtf32 split GEMM (K2, K10)
// =====================================================================
template<int EPI, int SPLIT>
__global__ void __launch_bounds__(256) tgemm(
    const float* __restrict__ A, const float* __restrict__ B, float* __restrict__ C,
    int M, int N, int lda, int ldb, int ldc, int klen,
    const float* __restrict__ b1, const float* __restrict__ mask)
{
    extern __shared__ float sm[];
    float* sAhi = sm;
    float* sBhi = sm + 2 * ABUF;
    float* sAlo = sm + 4 * ABUF;
    float* sBlo = sm + 6 * ABUF;

    const int tid  = threadIdx.x;
    const int lane = tid & 31;
    const int wid  = tid >> 5;
    const int wm   = wid & 1;
    const int wn   = wid >> 1;
    const int bm   = blockIdx.y * 128;
    const int bn   = blockIdx.x * 128;
    const int kbeg = blockIdx.z * klen;

    int lrow[4], lq[4];
#pragma unroll
    for (int i = 0; i < 4; i++) {
        int idx = i * 256 + tid;
        lrow[i] = idx >> 3;
        lq[i]   = (idx & 7) * 4;
    }

    float c[4][4][4];
#pragma unroll
    for (int mi = 0; mi < 4; mi++)
#pragma unroll
        for (int ni = 0; ni < 4; ni++)
#pragma unroll
            for (int j = 0; j < 4; j++) c[mi][ni][j] = 0.f;

    float4 rA[4], rB[4];

    auto load_tile = [&](int kt) {
#pragma unroll
        for (int i = 0; i < 4; i++) {
            int kk = kbeg + kt + lq[i];
            rA[i] = *(const float4*)(A + (size_t)(bm + lrow[i]) * lda + kk);
            rB[i] = *(const float4*)(B + (size_t)(bn + lrow[i]) * ldb + kk);
        }
    };

    auto store_tile = [&](int buf) {
#pragma unroll
        for (int i = 0; i < 4; i++) {
            float4 a = rA[i], b = rB[i];
            float4 ah, bh;
            ah.x = to_tf32(a.x); ah.y = to_tf32(a.y); ah.z = to_tf32(a.z); ah.w = to_tf32(a.w);
            bh.x = to_tf32(b.x); bh.y = to_tf32(b.y); bh.z = to_tf32(b.z); bh.w = to_tf32(b.w);
            const int off = lrow[i] * SSTR + lq[i];
            *(float4*)(sAhi + buf * ABUF + off) = ah;
            *(float4*)(sBhi + buf * ABUF + off) = bh;
            if (SPLIT) {
                float4 al, bl;
                al.x = to_tf32(a.x - ah.x); al.y = to_tf32(a.y - ah.y);
                al.z = to_tf32(a.z - ah.z); al.w = to_tf32(a.w - ah.w);
                bl.x = to_tf32(b.x - bh.x); bl.y = to_tf32(b.y - bh.y);
                bl.z = to_tf32(b.z - bh.z); bl.w = to_tf32(b.w - bh.w);
                *(float4*)(sAlo + buf * ABUF + off) = al;
                *(float4*)(sBlo + buf * ABUF + off) = bl;
            }
        }
    };

    const int aoff = (wm * 64 + (lane >> 2)) * SSTR + (lane & 3);
    const int boff = (wn * 32 + (lane >> 2)) * SSTR + (lane & 3);

    auto compute = [&](int buf) {
#pragma unroll
        for (int ks = 0; ks < 4; ks++) {
            const int k0 = ks * 8;
            uint32_t afh[4][4], bfh[4][2];
            uint32_t afl[4][4], bfl[4][2];
#pragma unroll
            for (int mi = 0; mi < 4; mi++) {
                const float* ap = sAhi + buf * ABUF + aoff + mi * 16 * SSTR + k0;
                afh[mi][0] = __float_as_uint(ap[0]);
                afh[mi][1] = __float_as_uint(ap[8 * SSTR]);
                afh[mi][2] = __float_as_uint(ap[4]);
                afh[mi][3] = __float_as_uint(ap[8 * SSTR + 4]);
                if (SPLIT) {
                    const float* al = sAlo + buf * ABUF + aoff + mi * 16 * SSTR + k0;
                    afl[mi][0] = __float_as_uint(al[0]);
                    afl[mi][1] = __float_as_uint(al[8 * SSTR]);
                    afl[mi][2] = __float_as_uint(al[4]);
                    afl[mi][3] = __float_as_uint(al[8 * SSTR + 4]);
                }
            }
#pragma unroll
            for (int ni = 0; ni < 4; ni++) {
                const float* bp = sBhi + buf * ABUF + boff + ni * 8 * SSTR + k0;
                bfh[ni][0] = __float_as_uint(bp[0]);
                bfh[ni][1] = __float_as_uint(bp[4]);
                if (SPLIT) {
                    const float* bl = sBlo + buf * ABUF + boff + ni * 8 * SSTR + k0;
                    bfl[ni][0] = __float_as_uint(bl[0]);
                    bfl[ni][1] = __float_as_uint(bl[4]);
                }
            }
#pragma unroll
            for (int mi = 0; mi < 4; mi++)
#pragma unroll
                for (int ni = 0; ni < 4; ni++) {
                    if (SPLIT) {
                        asm volatile(
                            "mma.sync.aligned.m16n8k8.row.col.f32.tf32.tf32.f32 "
                            "{%0,%1,%2,%3}, {%4,%5,%6,%7}, {%8,%9}, {%0,%1,%2,%3};"
                            : "+f"(c[mi][ni][0]), "+f"(c[mi][ni][1]),
                              "+f"(c[mi][ni][2]), "+f"(c[mi][ni][3])
                            : "r"(afl[mi][0]), "r"(afl[mi][1]), "r"(afl[mi][2]), "r"(afl[mi][3]),
                              "r"(bfh[ni][0]), "r"(bfh[ni][1]));
                        asm volatile(
                            "mma.sync.aligned.m16n8k8.row.col.f32.tf32.tf32.f32 "
                            "{%0,%1,%2,%3}, {%4,%5,%6,%7}, {%8,%9}, {%0,%1,%2,%3};"
                            : "+f"(c[mi][ni][0]), "+f"(c[mi][ni][1]),
                              "+f"(c[mi][ni][2]), "+f"(c[mi][ni][3])
                            : "r"(afh[mi][0]), "r"(afh[mi][1]), "r"(afh[mi][2]), "r"(afh[mi][3]),
                              "r"(bfl[ni][0]), "r"(bfl[ni][1]));
                    }
                    asm volatile(
                        "mma.sync.aligned.m16n8k8.row.col.f32.tf32.tf32.f32 "
                        "{%0,%1,%2,%3}, {%4,%5,%6,%7}, {%8,%9}, {%0,%1,%2,%3};"
                        : "+f"(c[mi][ni][0]), "+f"(c[mi][ni][1]),
                          "+f"(c[mi][ni][2]), "+f"(c[mi][ni][3])
                        : "r"(afh[mi][0]), "r"(afh[mi][1]), "r"(afh[mi][2]), "r"(afh[mi][3]),
                          "r"(bfh[ni][0]), "r"(bfh[ni][1]));
                }
        }
    };

    load_tile(0);
    store_tile(0);
    __syncthreads();
    int buf = 0;
    for (int kt = 0; kt < klen; kt += 32) {
        const bool nxt = (kt + 32) < klen;
        if (nxt) load_tile(kt + 32);
        compute(buf);
        if (nxt) store_tile(buf ^ 1);
        __syncthreads();
        buf ^= 1;
    }

    float* Cp = C + (size_t)blockIdx.z * M * N;
#pragma unroll
    for (int mi = 0; mi < 4; mi++) {
        const int r0 = bm + wm * 64 + mi * 16 + (lane >> 2);
#pragma unroll
        for (int ni = 0; ni < 4; ni++) {
            const int col = bn + wn * 32 + ni * 8 + (lane & 3) * 2;
#pragma unroll
            for (int h = 0; h < 2; h++) {
                const int row = r0 + h * 8;
                float v0 = c[mi][ni][h * 2], v1 = c[mi][ni][h * 2 + 1];
                if (EPI == 1) { v0 += b1[col]; v1 += b1[col + 1]; }
                if (EPI == 3) {
                    const float* mp = mask + (size_t)row * ldc + col;
                    v0 = (mp[0] > 0.f) ? v0 : 0.f;
                    v1 = (mp[1] > 0.f) ? v1 : 0.f;
                }
                float2 o = {v0, v1};
                *(float2*)(Cp + (size_t)row * ldc + col) = o;
            }
        }
    }
}

// =====================================================================
// fp32 SIMT NT GEMM, split-K partials (K1)
// =====================================================================
constexpr int BM = 128, BN = 128, BK = 8, PADX = 4;

__global__ void __launch_bounds__(256) gemm_nt_f32_part(
    const float* __restrict__ A, const float* __restrict__ B, float* __restrict__ C,
    int M, int N, int klen, int lda, int ldb, int ldc)
{
    __shared__ __align__(16) float As[BK][BM + PADX];
    __shared__ __align__(16) float Bs[BK][BN + PADX];
    const int tid = threadIdx.x;
    const int tx = tid & 15, ty = tid >> 4;
    const int bm = blockIdx.y * BM, bn = blockIdx.x * BN;
    const int kbeg = blockIdx.z * klen;

    float acc[8][8];
#pragma unroll
    for (int i = 0; i < 8; i++)
#pragma unroll
        for (int j = 0; j < 8; j++) acc[i][j] = 0.f;

    for (int kt = 0; kt < klen; kt += BK) {
        {
            const int mm = tid >> 1;
            const int kq = (tid & 1) * 4;
            float4 av = *(const float4*)(A + (size_t)(bm + mm) * lda + (kbeg + kt + kq));
            As[kq + 0][mm] = av.x; As[kq + 1][mm] = av.y;
            As[kq + 2][mm] = av.z; As[kq + 3][mm] = av.w;
            float4 bv = *(const float4*)(B + (size_t)(bn + mm) * ldb + (kbeg + kt + kq));
            Bs[kq + 0][mm] = bv.x; Bs[kq + 1][mm] = bv.y;
            Bs[kq + 2][mm] = bv.z; Bs[kq + 3][mm] = bv.w;
        }
        __syncthreads();
#pragma unroll
        for (int kk = 0; kk < BK; kk++) {
            float4 a0 = *(float4*)&As[kk][ty * 8];
            float4 a1 = *(float4*)&As[kk][ty * 8 + 4];
            float4 b0 = *(float4*)&Bs[kk][tx * 8];
            float4 b1v = *(float4*)&Bs[kk][tx * 8 + 4];
            float a[8] = {a0.x, a0.y, a0.z, a0.w, a1.x, a1.y, a1.z, a1.w};
            float b[8] = {b0.x, b0.y, b0.z, b0.w, b1v.x, b1v.y, b1v.z, b1v.w};
#pragma unroll
            for (int i = 0; i < 8; i++)
#pragma unroll
                for (int j = 0; j < 8; j++) acc[i][j] += a[i] * b[j];
        }
        __syncthreads();
    }
    float* Cp = C + (size_t)blockIdx.z * M * N;
#pragma unroll
    for (int i = 0; i < 8; i++) {
        const int row = bm + ty * 8 + i;
#pragma unroll
        for (int jq = 0; jq < 8; jq += 4) {
            const int col = bn + tx * 8 + jq;
            float4 o = {acc[i][jq], acc[i][jq + 1], acc[i][jq + 2], acc[i][jq + 3]};
            *(float4*)(Cp + (size_t)row * ldc + col) = o;
        }
    }
}

__global__ void reduce_v(const float* __restrict__ part, const float* __restrict__ b1,
                         const float* __restrict__ b2, float* __restrict__ out)
{
    const int i = blockIdx.x * blockDim.x + threadIdx.x;
    if (i >= TOK * FD) return;
    float s = 0.f;
#pragma unroll
    for (int k = 0; k < 4; k++) s += part[(size_t)k * TOK * FD + i];
    const int col = i & 511;
    s += b1[col] + b2[col];
    out[i] = s > 0.f ? s : 0.f;
}

// =====================================================================
// transposes / converts
// =====================================================================
__global__ void transpose_k(const float* __restrict__ src, float* __restrict__ dst,
                            int R, int C)
{
    __shared__ float t[32][33];
    const int c0 = blockIdx.x * 32, r0 = blockIdx.y * 32;
#pragma unroll
    for (int i = threadIdx.y; i < 32; i += 8)
        t[i][threadIdx.x] = src[(size_t)(r0 + i) * C + (c0 + threadIdx.x)];
    __syncthreads();
#pragma unroll
    for (int i = threadIdx.y; i < 32; i += 8)
        dst[(size_t)(c0 + i) * R + (r0 + threadIdx.x)] = t[threadIdx.x][i];
}

__global__ void transpose_bf(const float* __restrict__ src, __nv_bfloat16* __restrict__ dst,
                             int R, int C)
{
    __shared__ float t[32][33];
    const int c0 = blockIdx.x * 32, r0 = blockIdx.y * 32;
#pragma unroll
    for (int i = threadIdx.y; i < 32; i += 8)
        t[i][threadIdx.x] = src[(size_t)(r0 + i) * C + (c0 + threadIdx.x)];
    __syncthreads();
#pragma unroll
    for (int i = threadIdx.y; i < 32; i += 8)
        dst[(size_t)(c0 + i) * R + (r0 + threadIdx.x)] = __float2bfloat16(t[threadIdx.x][i]);
}

__global__ void f2bf_k(const float* __restrict__ in, __nv_bfloat16* __restrict__ out, size_t n4)
{
    const size_t i = (size_t)blockIdx.x * blockDim.x + threadIdx.x;
    if (i >= n4) return;
    float4 x = *((const float4*)in + i);
    __nv_bfloat162 lo = __floats2bfloat162_rn(x.x, x.y);
    __nv_bfloat162 hi = __floats2bfloat162_rn(x.z, x.w);
    *((__nv_bfloat162*)out + i * 2)     = lo;
    *((__nv_bfloat162*)out + i * 2 + 1) = hi;
}

// =====================================================================
// SIMT TN GEMM
// =====================================================================
__global__ void __launch_bounds__(256) gemm_tn(
    const float* __restrict__ A, const float* __restrict__ B, float* __restrict__ C,
    int M, int N, int klen, int lda, int ldb, int ldc)
{
    __shared__ __align__(16) float As[BK][BM + PADX];
    __shared__ __align__(16) float Bs[BK][BN + PADX];
    const int tid = threadIdx.x;
    const int tx = tid & 15, ty = tid >> 4;
    const int bm = blockIdx.y * BM, bn = blockIdx.x * BN;
    const int kbeg = blockIdx.z * klen;

    float acc[8][8];
#pragma unroll
    for (int i = 0; i < 8; i++)
#pragma unroll
        for (int j = 0; j < 8; j++) acc[i][j] = 0.f;

    for (int kt = 0; kt < klen; kt += BK) {
        {
            const int kk = tid >> 5, mq = (tid & 31) * 4;
            *(float4*)&As[kk][mq] = *(const float4*)(A + (size_t)(kbeg + kt + kk) * lda + bm + mq);
            *(float4*)&Bs[kk][mq] = *(const float4*)(B + (size_t)(kbeg + kt + kk) * ldb + bn + mq);
        }
        __syncthreads();
#pragma unroll
        for (int kk = 0; kk < BK; kk++) {
            float4 a0 = *(float4*)&As[kk][ty * 8];
            float4 a1 = *(float4*)&As[kk][ty * 8 + 4];
            float4 b0 = *(float4*)&Bs[kk][tx * 8];
            float4 b1v = *(float4*)&Bs[kk][tx * 8 + 4];
            float a[8] = {a0.x, a0.y, a0.z, a0.w, a1.x, a1.y, a1.z, a1.w};
            float b[8] = {b0.x, b0.y, b0.z, b0.w, b1v.x, b1v.y, b1v.z, b1v.w};
#pragma unroll
            for (int i = 0; i < 8; i++)
#pragma unroll
                for (int j = 0; j < 8; j++) acc[i][j] += a[i] * b[j];
        }
        __syncthreads();
    }
    float* Cp = C + (size_t)blockIdx.z * M * N;
#pragma unroll
    for (int i = 0; i < 8; i++) {
        const int rr = bm + ty * 8 + i;
#pragma unroll
        for (int jq = 0; jq < 8; jq += 4) {
            const int cc = bn + tx * 8 + jq;
            float4 o = {acc[i][jq], acc[i][jq + 1], acc[i][jq + 2], acc[i][jq + 3]};
            *(float4*)(Cp + (size_t)rr * ldc + cc) = o;
        }
    }
}

// ---------------- LayerNorm forward (writes xhat fp32 + o bf16) ----------------
__global__ void ln_fwd(const float* __restrict__ x, float* __restrict__ xhat,
                       __nv_bfloat16* __restrict__ obf, float* __restrict__ rstd,
                       const float* __restrict__ gam, const float* __restrict__ bet)
{
    const int row = blockIdx.x, tid = threadIdx.x;
    const size_t base = (size_t)row * FD;
    float x0 = x[base + tid], x1 = x[base + tid + 256];
    __shared__ float r1[256], r2[256];
    r1[tid] = x0 + x1;
    r2[tid] = x0 * x0 + x1 * x1;
    __syncthreads();
    for (int s = 128; s > 0; s >>= 1) {
        if (tid < s) { r1[tid] += r1[tid + s]; r2[tid] += r2[tid + s]; }
        __syncthreads();
    }
    float mu  = r1[0] * (1.f / FD);
    float var = r2[0] * (1.f / FD) - mu * mu;
    float rs  = rsqrtf(var + 1e-5f);
    if (tid == 0) rstd[row] = rs;
    float h0 = (x0 - mu) * rs, h1 = (x1 - mu) * rs;
    xhat[base + tid]       = h0;
    xhat[base + tid + 256] = h1;
    obf[base + tid]       = __float2bfloat16(h0 * gam[tid]       + bet[tid]);
    obf[base + tid + 256] = __float2bfloat16(h1 * gam[tid + 256] + bet[tid + 256]);
}

// ---------------- LayerNorm backward ----------------
__global__ void ln_bwd(float* __restrict__ dio, const float* __restrict__ xhat,
                       const float* __restrict__ rstd, const float* __restrict__ gamma)
{
    const int row = blockIdx.x, tid = threadIdx.x;
    const size_t base = (size_t)row * FD;
    float d0 = dio[base + tid], d1 = dio[base + tid + 256];
    float h0 = xhat[base + tid], h1 = xhat[base + tid + 256];
    float dx0 = d0 * gamma[tid], dx1 = d1 * gamma[tid + 256];
    __shared__ float r1[256], r2[256];
    r1[tid] = dx0 + dx1;
    r2[tid] = dx0 * h0 + dx1 * h1;
    __syncthreads();
    for (int s = 128; s > 0; s >>= 1) {
        if (tid < s) { r1[tid] += r1[tid + s]; r2[tid] += r2[tid + s]; }
        __syncthreads();
    }
    float m1 = r1[0] * (1.f / FD);
    float m2 = r2[0] * (1.f / FD);
    float rs = rstd[row];
    dio[base + tid]       = rs * (dx0 - m1 - h0 * m2);
    dio[base + tid + 256] = rs * (dx1 - m1 - h1 * m2);
}

// ---------------- fast path pre-LN + LN (fp32 + bf16 out) ----------------
__global__ void fast_ln(const float* __restrict__ preo, const float* __restrict__ v,
                        const float* __restrict__ t, const float* __restrict__ gbp,
                        const float* __restrict__ step_b,
                        const float* __restrict__ gam, const float* __restrict__ bet,
                        float* __restrict__ xfo, __nv_bfloat16* __restrict__ xfbf)
{
    const int row = blockIdx.x, tid = threadIdx.x;
    const size_t base = (size_t)row * FD;
    float v0 = v[base + tid], v1 = v[base + tid + 256];
    __shared__ float r1[256], r2[256];
    r1[tid] = v0 * gbp[tid] + v1 * gbp[tid + 256];
    __syncthreads();
    for (int s = 128; s > 0; s >>= 1) {
        if (tid < s) r1[tid] += r1[tid + s];
        __syncthreads();
    }
    float sb = r1[0];
    __syncthreads();
    float x0 = preo[base + tid]       - v0 * t[base + tid]       - step_b[tid]       * v0 * sb;
    float x1 = preo[base + tid + 256] - v1 * t[base + tid + 256] - step_b[tid + 256] * v1 * sb;
    r1[tid] = x0 + x1;
    r2[tid] = x0 * x0 + x1 * x1;
    __syncthreads();
    for (int s = 128; s > 0; s >>= 1) {
        if (tid < s) { r1[tid] += r1[tid + s]; r2[tid] += r2[tid + s]; }
        __syncthreads();
    }
    float mu  = r1[0] * (1.f / FD);
    float var = r2[0] * (1.f / FD) - mu * mu;
    float rs  = rsqrtf(var + 1e-5f);
    float y0 = ((x0 - mu) * rs) * gam[tid]       + bet[tid];
    float y1 = ((x1 - mu) * rs) * gam[tid + 256] + bet[tid + 256];
    xfo[base + tid]        = y0;
    xfo[base + tid + 256]  = y1;
    xfbf[base + tid]       = __float2bfloat16(y0);
    xfbf[base + tid + 256] = __float2bfloat16(y1);
}

// ---------------- vu = v * u ----------------
__global__ void vu_mul(const float* __restrict__ v, const float* __restrict__ u,
                       float* __restrict__ vu)
{
    const int i = blockIdx.x * blockDim.x + threadIdx.x;
    if (i < TOK * FD) vu[i] = v[i] * u[i];
}

// ---------------- P(bf16) = exp(L - m[row]) * iz[row] ----------------
__global__ void softmax_apply_bf(const float* __restrict__ L, const float* __restrict__ rowm,
                                 const float* __restrict__ rowiz,
                                 __nv_bfloat16* __restrict__ P)
{
    const size_t i = (size_t)blockIdx.x * blockDim.x + threadIdx.x;
    if (i >= (size_t)TOK * VD / 4) return;
    const int row = (int)(i / (VD / 4));
    const float m = rowm[row], iz = rowiz[row];
    float4 x = *((const float4*)L + i);
    x.x = __expf(x.x - m) * iz;
    x.y = __expf(x.y - m) * iz;
    x.z = __expf(x.z - m) * iz;
    x.w = __expf(x.w - m) * iz;
    *((__nv_bfloat162*)P + i * 2)     = __floats2bfloat162_rn(x.x, x.y);
    *((__nv_bfloat162*)P + i * 2 + 1) = __floats2bfloat162_rn(x.z, x.w);
}

// ---------------- combine row-stat partials ----------------
template<int MODE>
__global__ void rowstat_fin(const float* __restrict__ pmax, const float* __restrict__ psum,
                            int nt, const float* __restrict__ lablog,
                            float* __restrict__ out1, float* __restrict__ out2)
{
    const int row = blockIdx.x, tid = threadIdx.x;
    const float* pm = pmax + (size_t)row * nt;
    const float* ps = psum + (size_t)row * nt;
    float m = -1e30f, s = 0.f;
    for (int i = tid; i < nt; i += 256) {
        float m2 = pm[i], s2 = ps[i];
        float mo = fmaxf(m, m2);
        s = s * __expf(m - mo) + s2 * __expf(m2 - mo);
        m = mo;
    }
    __shared__ float sm_[256], sz_[256];
    sm_[tid] = m; sz_[tid] = s;
    __syncthreads();
    for (int st = 128; st > 0; st >>= 1) {
        if (tid < st) {
            float m2 = sm_[tid + st], s2 = sz_[tid + st];
            float mo = fmaxf(sm_[tid], m2);
            sz_[tid] = sz_[tid] * __expf(sm_[tid] - mo) + s2 * __expf(m2 - mo);
            sm_[tid] = mo;
        }
        __syncthreads();
    }
    if (tid == 0) {
        if (MODE == 0) { out1[row] = sm_[0]; out2[row] = 1.f / sz_[0]; }
        else           { out1[row] = sm_[0] + logf(sz_[0]) - lablog[row]; }
    }
}

// ---------------- label logit ----------------
__global__ void label_logit(const float* __restrict__ X, const float* __restrict__ E,
                            const float* __restrict__ ob, const int* __restrict__ lab,
                            float* __restrict__ out)
{
    const int row  = blockIdx.x * 8 + (threadIdx.x >> 5);
    const int lane = threadIdx.x & 31;
    const int l = lab[row];
    const float4* x = (const float4*)(X + (size_t)row * FD);
    const float4* e = (const float4*)(E + (size_t)l * FD);
    float s = 0.f;
#pragma unroll
    for (int i = lane; i < FD / 4; i += 32) {
        float4 a = x[i], b = e[i];
        s += a.x * b.x + a.y * b.y + a.z * b.z + a.w * b.w;
    }
#pragma unroll
    for (int o = 16; o > 0; o >>= 1) s += __shfl_xor_sync(0xffffffff, s, o);
    if (lane == 0) out[row] = s + ob[l];
}

// ---------------- column sums ----------------
__global__ void colsum_part(const float* __restrict__ X, float* __restrict__ part)
{
    const int col = blockIdx.x * 256 + threadIdx.x;
    const int rc  = blockIdx.y;
    float s = 0.f;
    const int r0 = rc * 128;
#pragma unroll 4
    for (int b = 0; b < 128; b++) s += X[(size_t)(r0 + b) * FD + col];
    part[rc * FD + col] = s;
}
__global__ void colsum_fin(const float* __restrict__ part, float* __restrict__ out)
{
    const int col = blockIdx.x * 256 + threadIdx.x;
    float s = 0.f;
#pragma unroll
    for (int k = 0; k < 16; k++) s += part[k * FD + col];
    out[col] = s;
}

// ---------------- split-K reducers ----------------
__global__ void reduce_do(const float* __restrict__ part, const float* __restrict__ E,
                          const int* __restrict__ labels, float* __restrict__ out)
{
    const int i = blockIdx.x * blockDim.x + threadIdx.x;
    if (i >= TOK * FD) return;
    float s = 0.f;
#pragma unroll
    for (int k = 0; k < 4; k++) s += part[(size_t)k * TOK * FD + i];
    const int row = i >> 9, col = i & 511;
    out[i] = s - E[(size_t)labels[row] * FD + col];
}

__global__ void reduce_part16(const float* __restrict__ part, float* __restrict__ out, int n)
{
    const int i = blockIdx.x * blockDim.x + threadIdx.x;
    if (i >= n) return;
    float s = 0.f;
#pragma unroll
    for (int k = 0; k < 16; k++) s += part[(size_t)k * n + i];
    out[i] = s;
}

// ---------------- launch ----------------
extern "C" void kernel_launch(void* const* d_in, const int* in_sizes, int n_in,
                              void* d_out, int out_size)
{
    const float* h_  = (const float*)d_in[0];
    const float* E   = (const float*)d_in[1];
    const float* ob  = (const float*)d_in[2];
    const int*   lab = (const int*)  d_in[3];
    const float* Wh  = (const float*)d_in[4];
    const float* bh  = (const float*)d_in[5];
    const float* hb  = (const float*)d_in[6];
    const float* Wp  = (const float*)d_in[7];
    const float* bp  = (const float*)d_in[8];
    const float* gam = (const float*)d_in[9];
    const float* bet = (const float*)d_in[10];
    const float* sW  = (const float*)d_in[11];
    const float* sb  = (const float*)d_in[12];

    float* out    = (float*)d_out;
    float* o_loss = out;
    float* o_gWh  = out + 2048;
    float* o_ghb  = o_gWh + 512 * 1024;
    float* o_gWp  = o_ghb + 512;
    float* o_gbp  = o_gWp + 512 * 512;

    float *pv, *ppreo, *pxhat, *prstd, *pdo, *pdv, *pu, *pt, *pxf, *plog, *pm, *piz,
          *ppart, *pwt1, *pwt2, *pcs, *ppmax, *ppsum, *plabl;
    __nv_bfloat16 *pEbf, *pEtbf, *pobf, *pxfbf, *pPbf;
    cudaGetSymbolAddress((void**)&pv,    g_v);
    cudaGetSymbolAddress((void**)&ppreo, g_preo);
    cudaGetSymbolAddress((void**)&pxhat, g_xhat);
    cudaGetSymbolAddress((void**)&prstd, g_rstd);
    cudaGetSymbolAddress((void**)&pdo,   g_do);
    cudaGetSymbolAddress((void**)&pdv,   g_dv);
    cudaGetSymbolAddress((void**)&pu,    g_u);
    cudaGetSymbolAddress((void**)&pt,    g_t);
    cudaGetSymbolAddress((void**)&pxf,   g_xf);
    cudaGetSymbolAddress((void**)&plog,  g_logits);
    cudaGetSymbolAddress((void**)&pm,    g_rowm);
    cudaGetSymbolAddress((void**)&piz,   g_rowiz);
    cudaGetSymbolAddress((void**)&ppart, g_part);
    cudaGetSymbolAddress((void**)&pwt1,  g_wt1);
    cudaGetSymbolAddress((void**)&pwt2,  g_wt2);
    cudaGetSymbolAddress((void**)&pcs,   g_csum);
    cudaGetSymbolAddress((void**)&ppmax, g_pmax);
    cudaGetSymbolAddress((void**)&ppsum, g_psum);
    cudaGetSymbolAddress((void**)&plabl, g_lablog);
    cudaGetSymbolAddress((void**)&pEbf,  g_Ebf);
    cudaGetSymbolAddress((void**)&pEtbf, g_Etbf);
    cudaGetSymbolAddress((void**)&pobf,  g_obf);
    cudaGetSymbolAddress((void**)&pxfbf, g_xfbf);
    cudaGetSymbolAddress((void**)&pPbf,  g_Pbf);

    cudaFuncSetAttribute((const void*)tgemm<1,1>,    cudaFuncAttributeMaxDynamicSharedMemorySize, SM_SPLIT);
    cudaFuncSetAttribute((const void*)tgemm<3,1>,    cudaFuncAttributeMaxDynamicSharedMemorySize, SM_SPLIT);
    cudaFuncSetAttribute((const void*)tgemm2<0,0>,   cudaFuncAttributeMaxDynamicSharedMemorySize, SM_SINGLE);
    cudaFuncSetAttribute((const void*)tgemm2b<1,1>,  cudaFuncAttributeMaxDynamicSharedMemorySize, SM_BF);
    cudaFuncSetAttribute((const void*)tgemm2b<0,0>,  cudaFuncAttributeMaxDynamicSharedMemorySize, SM_BF);
    cudaFuncSetAttribute((const void*)tgemm2b<1,2>,  cudaFuncAttributeMaxDynamicSharedMemorySize, SM_BF);

    // T0: converts + transposes
    f2bf_k<<<((size_t)VD*FD/4 + 255)/256, 256>>>(E, pEbf, (size_t)VD*FD/4);
    transpose_bf<<<dim3(FD/32, VD/32), dim3(32,8)>>>(E, pEtbf, VD, FD);
    transpose_k<<<dim3(FD/32, FD/32), dim3(32,8)>>>(Wp, pwt1, FD, FD);

    // K1: v = relu(h @ Wh^T + bh + hb)   [fp32 split-K 4: exact relu masks]
    gemm_nt_f32_part<<<dim3(FD/BN, TOK/BM, 4), 256>>>(
        h_, Wh, ppart, TOK, FD, 256, HD, HD, FD);
    reduce_v<<<(TOK*FD + 255)/256, 256>>>(ppart, bh, hb, pv);

    // K2: pre_o = v @ Wp^T + bp          [3xtf32]
    tgemm<1,1><<<dim3(FD/128, TOK/128, 1), 256, SM_SPLIT>>>(
        pv, Wp, ppreo, TOK, FD, FD, FD, FD, FD, bp, nullptr);

    // K3: LN forward (xhat fp32, o bf16)
    ln_fwd<<<TOK, 256>>>(ppreo, pxhat, pobf, prstd, gam, bet);

    // K4: logits = o @ E^T + ob   [bf16, m-fast raster: A L2-resident]
    tgemm2b<1,1><<<dim3(TOK/128, VD/128, 1), 256, SM_BF>>>(
        pobf, pEbf, plog, TOK, VD, FD, FD, VD, FD, ob, ppmax, ppsum, NTV);

    // K5: combine partials -> rowm, rowiz
    rowstat_fin<0><<<TOK, 256>>>(ppmax, ppsum, NTV, nullptr, pm, piz);

    // K5b: P = softmax(logits) -> bf16
    softmax_apply_bf<<<(TOK*(VD/4) + 255)/256, 256>>>(plog, pm, piz, pPbf);

    // K6: do_part = P @ Et^T   [bf16, split-K 4, m-fast]
    tgemm2b<0,0><<<dim3(TOK/128, FD/128, 4), 256, SM_BF>>>(
        pPbf, pEtbf, ppart, TOK, FD, VD, VD, FD, 8000, nullptr, nullptr, nullptr, 0);
    reduce_do<<<(TOK*FD + 255)/256, 256>>>(ppart, E, lab, pdo);

    // K7: LN backward
    ln_bwd<<<TOK, 256>>>(pdo, pxhat, prstd, gam);

    // K8: gbp
    colsum_part<<<dim3(FD/256, 16), 256>>>(pdo, pcs);
    colsum_fin<<<FD/256, 256>>>(pcs, o_gbp);

    // K9: gWp = dpre_o^T @ v   (SIMT fp32 TN split-K 16)
    gemm_tn<<<dim3(FD/BN, FD/BM, 16), 256>>>(pdo, pv, ppart, FD, FD, 128, FD, FD, FD);
    reduce_part16<<<(FD*FD + 255)/256, 256>>>(ppart, o_gWp, FD*FD);

    // T1: gWpT
    transpose_k<<<dim3(FD/32, FD/32), dim3(32,8)>>>(o_gWp, pwt2, FD, FD);

    // K10: dpre_v = (dpre_o @ Wp) * (v>0)   [3xtf32]
    tgemm<3,1><<<dim3(FD/128, TOK/128, 1), 256, SM_SPLIT>>>(
        pdo, pwt1, pdv, TOK, FD, FD, FD, FD, FD, nullptr, pv);

    // K11: gWh = dpre_v^T @ h   (SIMT fp32 TN split-K 16)
    gemm_tn<<<dim3(HD/BN, FD/BM, 16), 256>>>(pdv, h_, ppart, FD, HD, 128, FD, HD, HD);
    reduce_part16<<<(FD*HD + 255)/256, 256>>>(ppart, o_gWh, FD*HD);

    // K12: ghb
    colsum_part<<<dim3(FD/256, 16), 256>>>(pdv, pcs);
    colsum_fin<<<FD/256, 256>>>(pcs, o_ghb);

    // K13: u = v @ gWp   [tf32]
    tgemm2<0,0><<<dim3(FD/128, TOK/128, 1), 256, SM_SINGLE>>>(
        pv, pwt2, pu, TOK, FD, FD, FD, FD, FD, nullptr, nullptr, nullptr, 0);

    // K13b: vu = v * u  (into g_do)
    vu_mul<<<(TOK*FD + 255)/256, 256>>>(pv, pu, pdo);

    // K14: t = vu @ step_W^T   [tf32]
    tgemm2<0,0><<<dim3(FD/128, TOK/128, 1), 256, SM_SINGLE>>>(
        pdo, sW, pt, TOK, FD, FD, FD, FD, FD, nullptr, nullptr, nullptr, 0);

    // K15: fast pre-LN + LN -> xf (fp32 + bf16)
    fast_ln<<<TOK, 256>>>(ppreo, pv, pt, o_gbp, sb, gam, bet, pxf, pxfbf);

    // K16: fast logits stats only  [bf16, m-fast, STAT=2]
    tgemm2b<1,2><<<dim3(TOK/128, VD/128, 1), 256, SM_BF>>>(
        pxfbf, pEbf, nullptr, TOK, VD, FD, FD, VD, FD, ob, ppmax, ppsum, NTV);

    // K16b: exact label logit (fp32 dot)
    label_logit<<<TOK/8, 256>>>(pxf, E, ob, lab, plabl);

    // K17: fast loss
    rowstat_fin<1><<<TOK, 256>>>(ppmax, ppsum, NTV, plabl, o_loss, nullptr);
}

// round 15
// speedup vs baseline: 1.0156x; 1.0156x over previous
#include <cuda_runtime.h>
#include <cuda_bf16.h>
#include <math.h>
#include <stdint.h>

#define TOK 2048
#define HD  1024
#define FD  512
#define VD  32000
#define NTV (VD/128)   // 250 column tiles for V-GEMMs

// ---------------- scratch (__device__ globals) ----------------
__device__ float g_v    [TOK*FD];
__device__ float g_preo [TOK*FD];
__device__ float g_xhat [TOK*FD];
__device__ float g_rstd [TOK];
__device__ float g_do   [TOK*FD];   // dpre_o, then vu
__device__ float g_dv   [TOK*FD];
__device__ float g_t    [TOK*FD];
__device__ float g_xf   [TOK*FD];
__device__ float g_logits[(size_t)TOK*VD];
__device__ float g_rowm [TOK];
__device__ float g_rowiz[TOK];
__device__ float g_part [16*FD*HD];
__device__ float g_wt1  [FD*FD];
__device__ float g_wt2  [FD*FD];
__device__ float g_csum [16*FD];
__device__ float g_pmax [TOK*NTV];
__device__ float g_psum [TOK*NTV];
__device__ __nv_bfloat16 g_Ebf [(size_t)VD*FD];
__device__ __nv_bfloat16 g_Etbf[(size_t)FD*VD];
__device__ __nv_bfloat16 g_obf [TOK*FD];
__device__ __nv_bfloat16 g_xfbf[TOK*FD];
__device__ __nv_bfloat16 g_Pbf [(size_t)TOK*VD];

__device__ __forceinline__ float to_tf32(float x){
    float y; asm("cvt.rna.tf32.f32 %0, %1;" : "=f"(y) : "f"(x)); return y;
}
__device__ __forceinline__ void cp_async16(void* sdst, const void* gsrc){
    uint32_t s = (uint32_t)__cvta_generic_to_shared(sdst);
    asm volatile("cp.async.cg.shared.global [%0], [%1], 16;" :: "r"(s), "l"(gsrc) : "memory");
}

constexpr int SSTR = 36;
constexpr int ABUF = 128 * SSTR;
constexpr int SM_SINGLE = 4 * ABUF * 4;    // tgemm2 tf32
constexpr int SM_SPLIT  = 8 * ABUF * 4;    // tgemm split
constexpr int WSTR  = 20;
constexpr int ABUFW = 128 * WSTR;
constexpr int SM_BF = 4 * ABUFW * 4;       // 40960 B

// =====================================================================
// tgemm2b: bf16 m16n8k16 GEMM, occ-2, cp.async (R12 champion config).
// C = A @ B^T (f32 accum). A [M,K] bf16, B [N,K] bf16. 128x128x32 tiles.
// GRID: blockIdx.x = N tile, blockIdx.y = M tile, blockIdx.z = split-K.
// EPI: 0 none | 1 +b1[col]
// STAT: 0 none | 1 write C + partials | 2 partials only
// =====================================================================
template<int EPI, int STAT>
__global__ void __launch_bounds__(256, 2) tgemm2b(
    const __nv_bfloat16* __restrict__ A, const __nv_bfloat16* __restrict__ B,
    float* __restrict__ C,
    int M, int N, int lda, int ldb, int ldc, int klen,
    const float* __restrict__ b1,
    float* __restrict__ pmax, float* __restrict__ psum, int ntil)
{
    extern __shared__ uint32_t smw[];
    uint32_t* sA = smw;
    uint32_t* sB = smw + 2 * ABUFW;

    const int tid  = threadIdx.x;
    const int lane = tid & 31;
    const int wid  = tid >> 5;
    const int wm   = wid & 1;
    const int wn   = wid >> 1;
    const int bm   = blockIdx.y * 128;
    const int bn   = blockIdx.x * 128;
    const int kbeg = blockIdx.z * klen;

    int crow[2], cc[2];
#pragma unroll
    for (int i = 0; i < 2; i++) {
        int idx = i * 256 + tid;
        crow[i] = idx >> 2;
        cc[i]   = idx & 3;
    }

    float c[4][4][4];
#pragma unroll
    for (int mi = 0; mi < 4; mi++)
#pragma unroll
        for (int ni = 0; ni < 4; ni++)
#pragma unroll
            for (int j = 0; j < 4; j++) c[mi][ni][j] = 0.f;

    auto issue = [&](int kt, int buf) {
#pragma unroll
        for (int i = 0; i < 2; i++) {
            const int kk = kbeg + kt + cc[i] * 8;
            cp_async16(sA + buf * ABUFW + crow[i] * WSTR + cc[i] * 4,
                       A + (size_t)(bm + crow[i]) * lda + kk);
            cp_async16(sB + buf * ABUFW + crow[i] * WSTR + cc[i] * 4,
                       B + (size_t)(bn + crow[i]) * ldb + kk);
        }
        asm volatile("cp.async.commit_group;" ::: "memory");
    };

    const int q    = lane & 3;
    const int aoff = (wm * 64 + (lane >> 2)) * WSTR + q;
    const int boff = (wn * 32 + (lane >> 2)) * WSTR + q;

    auto compute = [&](int buf) {
#pragma unroll
        for (int ks = 0; ks < 2; ks++) {
            const int k0 = ks * 8;
            uint32_t af[4][4], bf[4][2];
#pragma unroll
            for (int mi = 0; mi < 4; mi++) {
                const uint32_t* ap = sA + buf * ABUFW + aoff + mi * 16 * WSTR + k0;
                af[mi][0] = ap[0];
                af[mi][1] = ap[8 * WSTR];
                af[mi][2] = ap[4];
                af[mi][3] = ap[8 * WSTR + 4];
            }
#pragma unroll
            for (int ni = 0; ni < 4; ni++) {
                const uint32_t* bp = sB + buf * ABUFW + boff + ni * 8 * WSTR + k0;
                bf[ni][0] = bp[0];
                bf[ni][1] = bp[4];
            }
#pragma unroll
            for (int mi = 0; mi < 4; mi++)
#pragma unroll
                for (int ni = 0; ni < 4; ni++) {
                    asm volatile(
                        "mma.sync.aligned.m16n8k16.row.col.f32.bf16.bf16.f32 "
                        "{%0,%1,%2,%3}, {%4,%5,%6,%7}, {%8,%9}, {%0,%1,%2,%3};"
                        : "+f"(c[mi][ni][0]), "+f"(c[mi][ni][1]),
                          "+f"(c[mi][ni][2]), "+f"(c[mi][ni][3])
                        : "r"(af[mi][0]), "r"(af[mi][1]), "r"(af[mi][2]), "r"(af[mi][3]),
                          "r"(bf[ni][0]), "r"(bf[ni][1]));
                }
        }
    };

    issue(0, 0);
    int buf = 0;
    for (int kt = 0; kt < klen; kt += 32) {
        const bool nxt = (kt + 32) < klen;
        if (nxt) {
            issue(kt + 32, buf ^ 1);
            asm volatile("cp.async.wait_group 1;" ::: "memory");
        } else {
            asm volatile("cp.async.wait_group 0;" ::: "memory");
        }
        __syncthreads();
        compute(buf);
        __syncthreads();
        buf ^= 1;
    }

    if (EPI == 1) {
#pragma unroll
        for (int mi = 0; mi < 4; mi++)
#pragma unroll
            for (int ni = 0; ni < 4; ni++) {
                const int col = bn + wn * 32 + ni * 8 + (lane & 3) * 2;
                float bb0 = b1[col], bb1 = b1[col + 1];
                c[mi][ni][0] += bb0; c[mi][ni][1] += bb1;
                c[mi][ni][2] += bb0; c[mi][ni][3] += bb1;
            }
    }

    if (STAT != 2) {
        float* Cp = C + (size_t)blockIdx.z * M * N;
#pragma unroll
        for (int mi = 0; mi < 4; mi++) {
            const int r0 = bm + wm * 64 + mi * 16 + (lane >> 2);
#pragma unroll
            for (int ni = 0; ni < 4; ni++) {
                const int col = bn + wn * 32 + ni * 8 + (lane & 3) * 2;
#pragma unroll
                for (int h = 0; h < 2; h++) {
                    float2 o = {c[mi][ni][h * 2], c[mi][ni][h * 2 + 1]};
                    *(float2*)(Cp + (size_t)(r0 + h * 8) * ldc + col) = o;
                }
            }
        }
    }

    if (STAT) {
        float* smax = (float*)smw;
        float* ssum = (float*)smw + 512;
        __syncthreads();
#pragma unroll
        for (int mi = 0; mi < 4; mi++)
#pragma unroll
            for (int h = 0; h < 2; h++) {
                float m = -1e30f, s = 0.f;
#pragma unroll
                for (int ni = 0; ni < 4; ni++)
#pragma unroll
                    for (int j = 0; j < 2; j++) {
                        float x = c[mi][ni][h * 2 + j];
                        float mn = fmaxf(m, x);
                        s = s * __expf(m - mn) + __expf(x - mn);
                        m = mn;
                    }
#pragma unroll
                for (int o = 1; o <= 2; o <<= 1) {
                    float m2 = __shfl_xor_sync(0xffffffff, m, o);
                    float s2 = __shfl_xor_sync(0xffffffff, s, o);
                    float mo = fmaxf(m, m2);
                    s = s * __expf(m - mo) + s2 * __expf(m2 - mo);
                    m = mo;
                }
                if ((lane & 3) == 0) {
                    int rl = wm * 64 + mi * 16 + (lane >> 2) + h * 8;
                    smax[wn * 128 + rl] = m;
                    ssum[wn * 128 + rl] = s;
                }
            }
        __syncthreads();
        if (tid < 128) {
            float m = smax[tid], s = ssum[tid];
#pragma unroll
            for (int w = 1; w < 4; w++) {
                float m2 = smax[w * 128 + tid], s2 = ssum[w * 128 + tid];
                float mo = fmaxf(m, m2);
                s = s * __expf(m - mo) + s2 * __expf(m2 - mo);
                m = mo;
            }
            pmax[(size_t)(bm + tid) * ntil + blockIdx.x] = m;
            psum[(size_t)(bm + tid) * ntil + blockIdx.x] = s;
        }
    }
}

// =====================================================================
// tgemm2: occ-2 single-tf32 GEMM (K13/K14)
// EPI: 0 none | 2 multiply elementwise by m1[row*ldc+col] (vu fusion)
// =====================================================================
template<int EPI>
__global__ void __launch_bounds__(256, 2) tgemm2(
    const float* __restrict__ A, const float* __restrict__ B, float* __restrict__ C,
    int M, int N, int lda, int ldb, int ldc, int klen,
    const float* __restrict__ m1)
{
    extern __shared__ float sm[];
    float* sA = sm;
    float* sB = sm + 2 * ABUF;

    const int tid  = threadIdx.x;
    const int lane = tid & 31;
    const int wid  = tid >> 5;
    const int wm   = wid & 1;
    const int wn   = wid >> 1;
    const int bm   = blockIdx.y * 128;
    const int bn   = blockIdx.x * 128;
    const int kbeg = blockIdx.z * klen;

    int lrow[4], lq[4];
#pragma unroll
    for (int i = 0; i < 4; i++) {
        int idx = i * 256 + tid;
        lrow[i] = idx >> 3;
        lq[i]   = (idx & 7) * 4;
    }

    float c[4][4][4];
#pragma unroll
    for (int mi = 0; mi < 4; mi++)
#pragma unroll
        for (int ni = 0; ni < 4; ni++)
#pragma unroll
            for (int j = 0; j < 4; j++) c[mi][ni][j] = 0.f;

    auto issue = [&](int kt, int buf) {
#pragma unroll
        for (int i = 0; i < 4; i++) {
            const int kk = kbeg + kt + lq[i];
            const int off = buf * ABUF + lrow[i] * SSTR + lq[i];
            cp_async16(sA + off, A + (size_t)(bm + lrow[i]) * lda + kk);
            cp_async16(sB + off, B + (size_t)(bn + lrow[i]) * ldb + kk);
        }
        asm volatile("cp.async.commit_group;" ::: "memory");
    };

    const int aoff = (wm * 64 + (lane >> 2)) * SSTR + (lane & 3);
    const int boff = (wn * 32 + (lane >> 2)) * SSTR + (lane & 3);

    auto compute = [&](int buf) {
#pragma unroll
        for (int ks = 0; ks < 4; ks++) {
            const int k0 = ks * 8;
            uint32_t af[4][4], bf[4][2];
#pragma unroll
            for (int mi = 0; mi < 4; mi++) {
                const float* ap = sA + buf * ABUF + aoff + mi * 16 * SSTR + k0;
                af[mi][0] = __float_as_uint(ap[0]);
                af[mi][1] = __float_as_uint(ap[8 * SSTR]);
                af[mi][2] = __float_as_uint(ap[4]);
                af[mi][3] = __float_as_uint(ap[8 * SSTR + 4]);
            }
#pragma unroll
            for (int ni = 0; ni < 4; ni++) {
                const float* bp = sB + buf * ABUF + boff + ni * 8 * SSTR + k0;
                bf[ni][0] = __float_as_uint(bp[0]);
                bf[ni][1] = __float_as_uint(bp[4]);
            }
#pragma unroll
            for (int mi = 0; mi < 4; mi++)
#pragma unroll
                for (int ni = 0; ni < 4; ni++) {
                    asm volatile(
                        "mma.sync.aligned.m16n8k8.row.col.f32.tf32.tf32.f32 "
                        "{%0,%1,%2,%3}, {%4,%5,%6,%7}, {%8,%9}, {%0,%1,%2,%3};"
                        : "+f"(c[mi][ni][0]), "+f"(c[mi][ni][1]),
                          "+f"(c[mi][ni][2]), "+f"(c[mi][ni][3])
                        : "r"(af[mi][0]), "r"(af[mi][1]), "r"(af[mi][2]), "r"(af[mi][3]),
                          "r"(bf[ni][0]), "r"(bf[ni][1]));
                }
        }
    };

    issue(0, 0);
    int buf = 0;
    for (int kt = 0; kt < klen; kt += 32) {
        const bool nxt = (kt + 32) < klen;
        if (nxt) {
            issue(kt + 32, buf ^ 1);
            asm volatile("cp.async.wait_group 1;" ::: "memory");
        } else {
            asm volatile("cp.async.wait_group 0;" ::: "memory");
        }
        __syncthreads();
        compute(buf);
        __syncthreads();
        buf ^= 1;
    }

    float* Cp = C;
#pragma unroll
    for (int mi = 0; mi < 4; mi++) {
        const int r0 = bm + wm * 64 + mi * 16 + (lane >> 2);
#pragma unroll
        for (int ni = 0; ni < 4; ni++) {
            const int col = bn + wn * 32 + ni * 8 + (lane & 3) * 2;
#pragma unroll
            for (int h = 0; h < 2; h++) {
                const int row = r0 + h * 8;
                float v0 = c[mi][ni][h * 2], v1 = c[mi][ni][h * 2 + 1];
                if (EPI == 2) {
                    const float* mp = m1 + (size_t)row * ldc + col;
                    v0 *= mp[0];
                    v1 *= mp[1];
                }
                float2 o = {v0, v1};
                *(float2*)(Cp + (size_t)row * ldc + col) = o;
            }
        }
    }
}

// =====================================================================
// 3xtf32 split GEMM (K2, K10)
// =====================================================================
template<int EPI, int SPLIT>
__global__ void __launch_bounds__(256) tgemm(
    const float* __restrict__ A, const float* __restrict__ B, float* __restrict__ C,
    int M, int N, int lda, int ldb, int ldc, int klen,
    const float* __restrict__ b1, const float* __restrict__ mask)
{
    extern __shared__ float sm[];
    float* sAhi = sm;
    float* sBhi = sm + 2 * ABUF;
    float* sAlo = sm + 4 * ABUF;
    float* sBlo = sm + 6 * ABUF;

    const int tid  = threadIdx.x;
    const int lane = tid & 31;
    const int wid  = tid >> 5;
    const int wm   = wid & 1;
    const int wn   = wid >> 1;
    const int bm   = blockIdx.y * 128;
    const int bn   = blockIdx.x * 128;
    const int kbeg = blockIdx.z * klen;

    int lrow[4], lq[4];
#pragma unroll
    for (int i = 0; i < 4; i++) {
        int idx = i * 256 + tid;
        lrow[i] = idx >> 3;
        lq[i]   = (idx & 7) * 4;
    }

    float c[4][4][4];
#pragma unroll
    for (int mi = 0; mi < 4; mi++)
#pragma unroll
        for (int ni = 0; ni < 4; ni++)
#pragma unroll
            for (int j = 0; j < 4; j++) c[mi][ni][j] = 0.f;

    float4 rA[4], rB[4];

    auto load_tile = [&](int kt) {
#pragma unroll
        for (int i = 0; i < 4; i++) {
            int kk = kbeg + kt + lq[i];
            rA[i] = *(const float4*)(A + (size_t)(bm + lrow[i]) * lda + kk);
            rB[i] = *(const float4*)(B + (size_t)(bn + lrow[i]) * ldb + kk);
        }
    };

    auto store_tile = [&](int buf) {
#pragma unroll
        for (int i = 0; i < 4; i++) {
            float4 a = rA[i], b = rB[i];
            float4 ah, bh;
            ah.x = to_tf32(a.x); ah.y = to_tf32(a.y); ah.z = to_tf32(a.z); ah.w = to_tf32(a.w);
            bh.x = to_tf32(b.x); bh.y = to_tf32(b.y); bh.z = to_tf32(b.z); bh.w = to_tf32(b.w);
            const int off = lrow[i] * SSTR + lq[i];
            *(float4*)(sAhi + buf * ABUF + off) = ah;
            *(float4*)(sBhi + buf * ABUF + off) = bh;
            if (SPLIT) {
                float4 al, bl;
                al.x = to_tf32(a.x - ah.x); al.y = to_tf32(a.y - ah.y);
                al.z = to_tf32(a.z - ah.z); al.w = to_tf32(a.w - ah.w);
                bl.x = to_tf32(b.x - bh.x); bl.y = to_tf32(b.y - bh.y);
                bl.z = to_tf32(b.z - bh.z); bl.w = to_tf32(b.w - bh.w);
                *(float4*)(sAlo + buf * ABUF + off) = al;
                *(float4*)(sBlo + buf * ABUF + off) = bl;
            }
        }
    };

    const int aoff = (wm * 64 + (lane >> 2)) * SSTR + (lane & 3);
    const int boff = (wn * 32 + (lane >> 2)) * SSTR + (lane & 3);

    auto compute = [&](int buf) {
#pragma unroll
        for (int ks = 0; ks < 4; ks++) {
            const int k0 = ks * 8;
            uint32_t afh[4][4], bfh[4][2];
            uint32_t afl[4][4], bfl[4][2];
#pragma unroll
            for (int mi = 0; mi < 4; mi++) {
                const float* ap = sAhi + buf * ABUF + aoff + mi * 16 * SSTR + k0;
                afh[mi][0] = __float_as_uint(ap[0]);
                afh[mi][1] = __float_as_uint(ap[8 * SSTR]);
                afh[mi][2] = __float_as_uint(ap[4]);
                afh[mi][3] = __float_as_uint(ap[8 * SSTR + 4]);
                if (SPLIT) {
                    const float* al = sAlo + buf * ABUF + aoff + mi * 16 * SSTR + k0;
                    afl[mi][0] = __float_as_uint(al[0]);
                    afl[mi][1] = __float_as_uint(al[8 * SSTR]);
                    afl[mi][2] = __float_as_uint(al[4]);
                    afl[mi][3] = __float_as_uint(al[8 * SSTR + 4]);
                }
            }
#pragma unroll
            for (int ni = 0; ni < 4; ni++) {
                const float* bp = sBhi + buf * ABUF + boff + ni * 8 * SSTR + k0;
                bfh[ni][0] = __float_as_uint(bp[0]);
                bfh[ni][1] = __float_as_uint(bp[4]);
                if (SPLIT) {
                    const float* bl = sBlo + buf * ABUF + boff + ni * 8 * SSTR + k0;
                    bfl[ni][0] = __float_as_uint(bl[0]);
                    bfl[ni][1] = __float_as_uint(bl[4]);
                }
            }
#pragma unroll
            for (int mi = 0; mi < 4; mi++)
#pragma unroll
                for (int ni = 0; ni < 4; ni++) {
                    if (SPLIT) {
                        asm volatile(
                            "mma.sync.aligned.m16n8k8.row.col.f32.tf32.tf32.f32 "
                            "{%0,%1,%2,%3}, {%4,%5,%6,%7}, {%8,%9}, {%0,%1,%2,%3};"
                            : "+f"(c[mi][ni][0]), "+f"(c[mi][ni][1]),
                              "+f"(c[mi][ni][2]), "+f"(c[mi][ni][3])
                            : "r"(afl[mi][0]), "r"(afl[mi][1]), "r"(afl[mi][2]), "r"(afl[mi][3]),
                              "r"(bfh[ni][0]), "r"(bfh[ni][1]));
                        asm volatile(
                            "mma.sync.aligned.m16n8k8.row.col.f32.tf32.tf32.f32 "
                            "{%0,%1,%2,%3}, {%4,%5,%6,%7}, {%8,%9}, {%0,%1,%2,%3};"
                            : "+f"(c[mi][ni][0]), "+f"(c[mi][ni][1]),
                              "+f"(c[mi][ni][2]), "+f"(c[mi][ni][3])
                            : "r"(afh[mi][0]), "r"(afh[mi][1]), "r"(afh[mi][2]), "r"(afh[mi][3]),
                              "r"(bfl[ni][0]), "r"(bfl[ni][1]));
                    }
                    asm volatile(
                        "mma.sync.aligned.m16n8k8.row.col.f32.tf32.tf32.f32 "
                        "{%0,%1,%2,%3}, {%4,%5,%6,%7}, {%8,%9}, {%0,%1,%2,%3};"
                        : "+f"(c[mi][ni][0]), "+f"(c[mi][ni][1]),
                          "+f"(c[mi][ni][2]), "+f"(c[mi][ni][3])
                        : "r"(afh[mi][0]), "r"(afh[mi][1]), "r"(afh[mi][2]), "r"(afh[mi][3]),
                          "r"(bfh[ni][0]), "r"(bfh[ni][1]));
                }
        }
    };

    load_tile(0);
    store_tile(0);
    __syncthreads();
    int buf = 0;
    for (int kt = 0; kt < klen; kt += 32) {
        const bool nxt = (kt + 32) < klen;
        if (nxt) load_tile(kt + 32);
        compute(buf);
        if (nxt) store_tile(buf ^ 1);
        __syncthreads();
        buf ^= 1;
    }

    float* Cp = C + (size_t)blockIdx.z * M * N;
#pragma unroll
    for (int mi = 0; mi < 4; mi++) {
        const int r0 = bm + wm * 64 + mi * 16 + (lane >> 2);
#pragma unroll
        for (int ni = 0; ni < 4; ni++) {
            const int col = bn + wn * 32 + ni * 8 + (lane & 3) * 2;
#pragma unroll
            for (int h = 0; h < 2; h++) {
                const int row = r0 + h * 8;
                float v0 = c[mi][ni][h * 2], v1 = c[mi][ni][h * 2 + 1];
                if (EPI == 1) { v0 += b1[col]; v1 += b1[col + 1]; }
                if (EPI == 3) {
                    const float* mp = mask + (size_t)row * ldc + col;
                    v0 = (mp[0] > 0.f) ? v0 : 0.f;
                    v1 = (mp[1] > 0.f) ? v1 : 0.f;
                }
                float2 o = {v0, v1};
                *(float2*)(Cp + (size_t)row * ldc + col) = o;
            }
        }
    }
}

// =====================================================================
// fp32 SIMT NT GEMM, split-K partials (K1)
// =====================================================================
constexpr int BM = 128, BN = 128, BK = 8, PADX = 4;

__global__ void __launch_bounds__(256) gemm_nt_f32_part(
    const float* __restrict__ A, const float* __restrict__ B, float* __restrict__ C,
    int M, int N, int klen, int lda, int ldb, int ldc)
{
    __shared__ __align__(16) float As[BK][BM + PADX];
    __shared__ __align__(16) float Bs[BK][BN + PADX];
    const int tid = threadIdx.x;
    const int tx = tid & 15, ty = tid >> 4;
    const int bm = blockIdx.y * BM, bn = blockIdx.x * BN;
    const int kbeg = blockIdx.z * klen;

    float acc[8][8];
#pragma unroll
    for (int i = 0; i < 8; i++)
#pragma unroll
        for (int j = 0; j < 8; j++) acc[i][j] = 0.f;

    for (int kt = 0; kt < klen; kt += BK) {
        {
            const int mm = tid >> 1;
            const int kq = (tid & 1) * 4;
            float4 av = *(const float4*)(A + (size_t)(bm + mm) * lda + (kbeg + kt + kq));
            As[kq + 0][mm] = av.x; As[kq + 1][mm] = av.y;
            As[kq + 2][mm] = av.z; As[kq + 3][mm] = av.w;
            float4 bv = *(const float4*)(B + (size_t)(bn + mm) * ldb + (kbeg + kt + kq));
            Bs[kq + 0][mm] = bv.x; Bs[kq + 1][mm] = bv.y;
            Bs[kq + 2][mm] = bv.z; Bs[kq + 3][mm] = bv.w;
        }
        __syncthreads();
#pragma unroll
        for (int kk = 0; kk < BK; kk++) {
            float4 a0 = *(float4*)&As[kk][ty * 8];
            float4 a1 = *(float4*)&As[kk][ty * 8 + 4];
            float4 b0 = *(float4*)&Bs[kk][tx * 8];
            float4 b1v = *(float4*)&Bs[kk][tx * 8 + 4];
            float a[8] = {a0.x, a0.y, a0.z, a0.w, a1.x, a1.y, a1.z, a1.w};
            float b[8] = {b0.x, b0.y, b0.z, b0.w, b1v.x, b1v.y, b1v.z, b1v.w};
#pragma unroll
            for (int i = 0; i < 8; i++)
#pragma unroll
                for (int j = 0; j < 8; j++) acc[i][j] += a[i] * b[j];
        }
        __syncthreads();
    }
    float* Cp = C + (size_t)blockIdx.z * M * N;
#pragma unroll
    for (int i = 0; i < 8; i++) {
        const int row = bm + ty * 8 + i;
#pragma unroll
        for (int jq = 0; jq < 8; jq += 4) {
            const int col = bn + tx * 8 + jq;
            float4 o = {acc[i][jq], acc[i][jq + 1], acc[i][jq + 2], acc[i][jq + 3]};
            *(float4*)(Cp + (size_t)row * ldc + col) = o;
        }
    }
}

__global__ void reduce_v(const float* __restrict__ part, const float* __restrict__ b1,
                         const float* __restrict__ b2, float* __restrict__ out)
{
    const int i = blockIdx.x * blockDim.x + threadIdx.x;
    if (i >= TOK * FD) return;
    float s = 0.f;
#pragma unroll
    for (int k = 0; k < 4; k++) s += part[(size_t)k * TOK * FD + i];
    const int col = i & 511;
    s += b1[col] + b2[col];
    out[i] = s > 0.f ? s : 0.f;
}

// =====================================================================
// transposes / converts
// =====================================================================
__global__ void transpose_k(const float* __restrict__ src, float* __restrict__ dst,
                            int R, int C)
{
    __shared__ float t[32][33];
    const int c0 = blockIdx.x * 32, r0 = blockIdx.y * 32;
#pragma unroll
    for (int i = threadIdx.y; i < 32; i += 8)
        t[i][threadIdx.x] = src[(size_t)(r0 + i) * C + (c0 + threadIdx.x)];
    __syncthreads();
#pragma unroll
    for (int i = threadIdx.y; i < 32; i += 8)
        dst[(size_t)(c0 + i) * R + (r0 + threadIdx.x)] = t[threadIdx.x][i];
}

__global__ void transpose_bf(const float* __restrict__ src, __nv_bfloat16* __restrict__ dst,
                             int R, int C)
{
    __shared__ float t[32][33];
    const int c0 = blockIdx.x * 32, r0 = blockIdx.y * 32;
#pragma unroll
    for (int i = threadIdx.y; i < 32; i += 8)
        t[i][threadIdx.x] = src[(size_t)(r0 + i) * C + (c0 + threadIdx.x)];
    __syncthreads();
#pragma unroll
    for (int i = threadIdx.y; i < 32; i += 8)
        dst[(size_t)(c0 + i) * R + (r0 + threadIdx.x)] = __float2bfloat16(t[threadIdx.x][i]);
}

__global__ void f2bf_k(const float* __restrict__ in, __nv_bfloat16* __restrict__ out, size_t n4)
{
    const size_t i = (size_t)blockIdx.x * blockDim.x + threadIdx.x;
    if (i >= n4) return;
    float4 x = *((const float4*)in + i);
    __nv_bfloat162 lo = __floats2bfloat162_rn(x.x, x.y);
    __nv_bfloat162 hi = __floats2bfloat162_rn(x.z, x.w);
    *((__nv_bfloat162*)out + i * 2)     = lo;
    *((__nv_bfloat162*)out + i * 2 + 1) = hi;
}

// =====================================================================
// SIMT TN GEMM
// =====================================================================
__global__ void __launch_bounds__(256) gemm_tn(
    const float* __restrict__ A, const float* __restrict__ B, float* __restrict__ C,
    int M, int N, int klen, int lda, int ldb, int ldc)
{
    __shared__ __align__(16) float As[BK][BM + PADX];
    __shared__ __align__(16) float Bs[BK][BN + PADX];
    const int tid = threadIdx.x;
    const int tx = tid & 15, ty = tid >> 4;
    const int bm = blockIdx.y * BM, bn = blockIdx.x * BN;
    const int kbeg = blockIdx.z * klen;

    float acc[8][8];
#pragma unroll
    for (int i = 0; i < 8; i++)
#pragma unroll
        for (int j = 0; j < 8; j++) acc[i][j] = 0.f;

    for (int kt = 0; kt < klen; kt += BK) {
        {
            const int kk = tid >> 5, mq = (tid & 31) * 4;
            *(float4*)&As[kk][mq] = *(const float4*)(A + (size_t)(kbeg + kt + kk) * lda + bm + mq);
            *(float4*)&Bs[kk][mq] = *(const float4*)(B + (size_t)(kbeg + kt + kk) * ldb + bn + mq);
        }
        __syncthreads();
#pragma unroll
        for (int kk = 0; kk < BK; kk++) {
            float4 a0 = *(float4*)&As[kk][ty * 8];
            float4 a1 = *(float4*)&As[kk][ty * 8 + 4];
            float4 b0 = *(float4*)&Bs[kk][tx * 8];
            float4 b1v = *(float4*)&Bs[kk][tx * 8 + 4];
            float a[8] = {a0.x, a0.y, a0.z, a0.w, a1.x, a1.y, a1.z, a1.w};
            float b[8] = {b0.x, b0.y, b0.z, b0.w, b1v.x, b1v.y, b1v.z, b1v.w};
#pragma unroll
            for (int i = 0; i < 8; i++)
#pragma unroll
                for (int j = 0; j < 8; j++) acc[i][j] += a[i] * b[j];
        }
        __syncthreads();
    }
    float* Cp = C + (size_t)blockIdx.z * M * N;
#pragma unroll
    for (int i = 0; i < 8; i++) {
        const int rr = bm + ty * 8 + i;
#pragma unroll
        for (int jq = 0; jq < 8; jq += 4) {
            const int cc = bn + tx * 8 + jq;
            float4 o = {acc[i][jq], acc[i][jq + 1], acc[i][jq + 2], acc[i][jq + 3]};
            *(float4*)(Cp + (size_t)rr * ldc + cc) = o;
        }
    }
}

// ---------------- LayerNorm forward (writes xhat fp32 + o bf16) ----------------
__global__ void ln_fwd(const float* __restrict__ x, float* __restrict__ xhat,
                       __nv_bfloat16* __restrict__ obf, float* __restrict__ rstd,
                       const float* __restrict__ gam, const float* __restrict__ bet)
{
    const int row = blockIdx.x, tid = threadIdx.x;
    const size_t base = (size_t)row * FD;
    float x0 = x[base + tid], x1 = x[base + tid + 256];
    __shared__ float r1[256], r2[256];
    r1[tid] = x0 + x1;
    r2[tid] = x0 * x0 + x1 * x1;
    __syncthreads();
    for (int s = 128; s > 0; s >>= 1) {
        if (tid < s) { r1[tid] += r1[tid + s]; r2[tid] += r2[tid + s]; }
        __syncthreads();
    }
    float mu  = r1[0] * (1.f / FD);
    float var = r2[0] * (1.f / FD) - mu * mu;
    float rs  = rsqrtf(var + 1e-5f);
    if (tid == 0) rstd[row] = rs;
    float h0 = (x0 - mu) * rs, h1 = (x1 - mu) * rs;
    xhat[base + tid]       = h0;
    xhat[base + tid + 256] = h1;
    obf[base + tid]       = __float2bfloat16(h0 * gam[tid]       + bet[tid]);
    obf[base + tid + 256] = __float2bfloat16(h1 * gam[tid + 256] + bet[tid + 256]);
}

// ---------------- fused: do = sum4(part) - E[lab] ; LN backward -> dio ----------------
__global__ void ln_bwd_fused(const float* __restrict__ part, const float* __restrict__ E,
                             const int* __restrict__ lab,
                             const float* __restrict__ xhat, const float* __restrict__ rstd,
                             const float* __restrict__ gamma, float* __restrict__ dio)
{
    const int row = blockIdx.x, tid = threadIdx.x;
    const size_t base = (size_t)row * FD;
    const int l = lab[row];
    float d0 = 0.f, d1 = 0.f;
#pragma unroll
    for (int k = 0; k < 4; k++) {
        d0 += part[(size_t)k * TOK * FD + base + tid];
        d1 += part[(size_t)k * TOK * FD + base + tid + 256];
    }
    d0 -= E[(size_t)l * FD + tid];
    d1 -= E[(size_t)l * FD + tid + 256];
    float h0 = xhat[base + tid], h1 = xhat[base + tid + 256];
    float dx0 = d0 * gamma[tid], dx1 = d1 * gamma[tid + 256];
    __shared__ float r1[256], r2[256];
    r1[tid] = dx0 + dx1;
    r2[tid] = dx0 * h0 + dx1 * h1;
    __syncthreads();
    for (int s = 128; s > 0; s >>= 1) {
        if (tid < s) { r1[tid] += r1[tid + s]; r2[tid] += r2[tid + s]; }
        __syncthreads();
    }
    float m1 = r1[0] * (1.f / FD);
    float m2 = r2[0] * (1.f / FD);
    float rs = rstd[row];
    dio[base + tid]       = rs * (dx0 - m1 - h0 * m2);
    dio[base + tid + 256] = rs * (dx1 - m1 - h1 * m2);
}

// ---------------- fast path pre-LN + LN (fp32 + bf16 out) ----------------
__global__ void fast_ln(const float* __restrict__ preo, const float* __restrict__ v,
                        const float* __restrict__ t, const float* __restrict__ gbp,
                        const float* __restrict__ step_b,
                        const float* __restrict__ gam, const float* __restrict__ bet,
                        float* __restrict__ xfo, __nv_bfloat16* __restrict__ xfbf)
{
    const int row = blockIdx.x, tid = threadIdx.x;
    const size_t base = (size_t)row * FD;
    float v0 = v[base + tid], v1 = v[base + tid + 256];
    __shared__ float r1[256], r2[256];
    r1[tid] = v0 * gbp[tid] + v1 * gbp[tid + 256];
    __syncthreads();
    for (int s = 128; s > 0; s >>= 1) {
        if (tid < s) r1[tid] += r1[tid + s];
        __syncthreads();
    }
    float sb = r1[0];
    __syncthreads();
    float x0 = preo[base + tid]       - v0 * t[base + tid]       - step_b[tid]       * v0 * sb;
    float x1 = preo[base + tid + 256] - v1 * t[base + tid + 256] - step_b[tid + 256] * v1 * sb;
    r1[tid] = x0 + x1;
    r2[tid] = x0 * x0 + x1 * x1;
    __syncthreads();
    for (int s = 128; s > 0; s >>= 1) {
        if (tid < s) { r1[tid] += r1[tid + s]; r2[tid] += r2[tid + s]; }
        __syncthreads();
    }
    float mu  = r1[0] * (1.f / FD);
    float var = r2[0] * (1.f / FD) - mu * mu;
    float rs  = rsqrtf(var + 1e-5f);
    float y0 = ((x0 - mu) * rs) * gam[tid]       + bet[tid];
    float y1 = ((x1 - mu) * rs) * gam[tid + 256] + bet[tid + 256];
    xfo[base + tid]        = y0;
    xfo[base + tid + 256]  = y1;
    xfbf[base + tid]       = __float2bfloat16(y0);
    xfbf[base + tid + 256] = __float2bfloat16(y1);
}

// ---------------- P(bf16) = exp(L - m[row]) * iz[row] ----------------
__global__ void softmax_apply_bf(const float* __restrict__ L, const float* __restrict__ rowm,
                                 const float* __restrict__ rowiz,
                                 __nv_bfloat16* __restrict__ P)
{
    const size_t i = (size_t)blockIdx.x * blockDim.x + threadIdx.x;
    if (i >= (size_t)TOK * VD / 4) return;
    const int row = (int)(i / (VD / 4));
    const float m = rowm[row], iz = rowiz[row];
    float4 x = *((const float4*)L + i);
    x.x = __expf(x.x - m) * iz;
    x.y = __expf(x.y - m) * iz;
    x.z = __expf(x.z - m) * iz;
    x.w = __expf(x.w - m) * iz;
    *((__nv_bfloat162*)P + i * 2)     = __floats2bfloat162_rn(x.x, x.y);
    *((__nv_bfloat162*)P + i * 2 + 1) = __floats2bfloat162_rn(x.z, x.w);
}

// ---------------- combine row-stat partials (softmax stats) ----------------
__global__ void rowstat_fin(const float* __restrict__ pmax, const float* __restrict__ psum,
                            int nt, float* __restrict__ out1, float* __restrict__ out2)
{
    const int row = blockIdx.x, tid = threadIdx.x;
    const float* pm = pmax + (size_t)row * nt;
    const float* ps = psum + (size_t)row * nt;
    float m = -1e30f, s = 0.f;
    for (int i = tid; i < nt; i += 256) {
        float m2 = pm[i], s2 = ps[i];
        float mo = fmaxf(m, m2);
        s = s * __expf(m - mo) + s2 * __expf(m2 - mo);
        m = mo;
    }
    __shared__ float sm_[256], sz_[256];
    sm_[tid] = m; sz_[tid] = s;
    __syncthreads();
    for (int st = 128; st > 0; st >>= 1) {
        if (tid < st) {
            float m2 = sm_[tid + st], s2 = sz_[tid + st];
            float mo = fmaxf(sm_[tid], m2);
            sz_[tid] = sz_[tid] * __expf(sm_[tid] - mo) + s2 * __expf(m2 - mo);
            sm_[tid] = mo;
        }
        __syncthreads();
    }
    if (tid == 0) { out1[row] = sm_[0]; out2[row] = 1.f / sz_[0]; }
}

// ---------------- fused fast loss: stats combine + exact fp32 label logit ----------------
__global__ void fast_loss_fin(const float* __restrict__ pmax, const float* __restrict__ psum,
                              int nt, const float* __restrict__ xf,
                              const float* __restrict__ E, const float* __restrict__ ob,
                              const int* __restrict__ lab, float* __restrict__ out)
{
    const int row = blockIdx.x, tid = threadIdx.x;
    const int l = lab[row];
    __shared__ float sm_[256], sz_[256];

    // exact label logit (fp32 dot over 512)
    {
        const size_t base = (size_t)row * FD;
        float p = xf[base + tid] * E[(size_t)l * FD + tid]
                + xf[base + tid + 256] * E[(size_t)l * FD + tid + 256];
        sm_[tid] = p;
        __syncthreads();
        for (int st = 128; st > 0; st >>= 1) {
            if (tid < st) sm_[tid] += sm_[tid + st];
            __syncthreads();
        }
    }
    __shared__ float lablog;
    if (tid == 0) lablog = sm_[0] + ob[l];
    __syncthreads();

    // combine stat partials
    const float* pm = pmax + (size_t)row * nt;
    const float* ps = psum + (size_t)row * nt;
    float m = -1e30f, s = 0.f;
    for (int i = tid; i < nt; i += 256) {
        float m2 = pm[i], s2 = ps[i];
        float mo = fmaxf(m, m2);
        s = s * __expf(m - mo) + s2 * __expf(m2 - mo);
        m = mo;
    }
    sm_[tid] = m; sz_[tid] = s;
    __syncthreads();
    for (int st = 128; st > 0; st >>= 1) {
        if (tid < st) {
            float m2 = sm_[tid + st], s2 = sz_[tid + st];
            float mo = fmaxf(sm_[tid], m2);
            sz_[tid] = sz_[tid] * __expf(sm_[tid] - mo) + s2 * __expf(m2 - mo);
            sm_[tid] = mo;
        }
        __syncthreads();
    }
    if (tid == 0) out[row] = sm_[0] + logf(sz_[0]) - lablog;
}

// ---------------- column sums ----------------
__global__ void colsum_part(const float* __restrict__ X, float* __restrict__ part)
{
    const int col = blockIdx.x * 256 + threadIdx.x;
    const int rc  = blockIdx.y;
    float s = 0.f;
    const int r0 = rc * 128;
#pragma unroll 4
    for (int b = 0; b < 128; b++) s += X[(size_t)(r0 + b) * FD + col];
    part[rc * FD + col] = s;
}
__global__ void colsum_fin(const float* __restrict__ part, float* __restrict__ out)
{
    const int col = blockIdx.x * 256 + threadIdx.x;
    float s = 0.f;
#pragma unroll
    for (int k = 0; k < 16; k++) s += part[k * FD + col];
    out[col] = s;
}

__global__ void reduce_part16(const float* __restrict__ part, float* __restrict__ out, int n)
{
    const int i = blockIdx.x * blockDim.x + threadIdx.x;
    if (i >= n) return;
    float s = 0.f;
#pragma unroll
    for (int k = 0; k < 16; k++) s += part[(size_t)k * n + i];
    out[i] = s;
}

// ---------------- launch ----------------
extern "C" void kernel_launch(void* const* d_in, const int* in_sizes, int n_in,
                              void* d_out, int out_size)
{
    const float* h_  = (const float*)d_in[0];
    const float* E   = (const float*)d_in[1];
    const float* ob  = (const float*)d_in[2];
    const int*   lab = (const int*)  d_in[3];
    const float* Wh  = (const float*)d_in[4];
    const float* bh  = (const float*)d_in[5];
    const float* hb  = (const float*)d_in[6];
    const float* Wp  = (const float*)d_in[7];
    const float* bp  = (const float*)d_in[8];
    const float* gam = (const float*)d_in[9];
    const float* bet = (const float*)d_in[10];
    const float* sW  = (const float*)d_in[11];
    const float* sb  = (const float*)d_in[12];

    float* out    = (float*)d_out;
    float* o_loss = out;
    float* o_gWh  = out + 2048;
    float* o_ghb  = o_gWh + 512 * 1024;
    float* o_gWp  = o_ghb + 512;
    float* o_gbp  = o_gWp + 512 * 512;

    float *pv, *ppreo, *pxhat, *prstd, *pdo, *pdv, *pt, *pxf, *plog, *pm, *piz,
          *ppart, *pwt1, *pwt2, *pcs, *ppmax, *ppsum;
    __nv_bfloat16 *pEbf, *pEtbf, *pobf, *pxfbf, *pPbf;
    cudaGetSymbolAddress((void**)&pv,    g_v);
    cudaGetSymbolAddress((void**)&ppreo, g_preo);
    cudaGetSymbolAddress((void**)&pxhat, g_xhat);
    cudaGetSymbolAddress((void**)&prstd, g_rstd);
    cudaGetSymbolAddress((void**)&pdo,   g_do);
    cudaGetSymbolAddress((void**)&pdv,   g_dv);
    cudaGetSymbolAddress((void**)&pt,    g_t);
    cudaGetSymbolAddress((void**)&pxf,   g_xf);
    cudaGetSymbolAddress((void**)&plog,  g_logits);
    cudaGetSymbolAddress((void**)&pm,    g_rowm);
    cudaGetSymbolAddress((void**)&piz,   g_rowiz);
    cudaGetSymbolAddress((void**)&ppart, g_part);
    cudaGetSymbolAddress((void**)&pwt1,  g_wt1);
    cudaGetSymbolAddress((void**)&pwt2,  g_wt2);
    cudaGetSymbolAddress((void**)&pcs,   g_csum);
    cudaGetSymbolAddress((void**)&ppmax, g_pmax);
    cudaGetSymbolAddress((void**)&ppsum, g_psum);
    cudaGetSymbolAddress((void**)&pEbf,  g_Ebf);
    cudaGetSymbolAddress((void**)&pEtbf, g_Etbf);
    cudaGetSymbolAddress((void**)&pobf,  g_obf);
    cudaGetSymbolAddress((void**)&pxfbf, g_xfbf);
    cudaGetSymbolAddress((void**)&pPbf,  g_Pbf);

    cudaFuncSetAttribute((const void*)tgemm<1,1>,    cudaFuncAttributeMaxDynamicSharedMemorySize, SM_SPLIT);
    cudaFuncSetAttribute((const void*)tgemm<3,1>,    cudaFuncAttributeMaxDynamicSharedMemorySize, SM_SPLIT);
    cudaFuncSetAttribute((const void*)tgemm2<0>,     cudaFuncAttributeMaxDynamicSharedMemorySize, SM_SINGLE);
    cudaFuncSetAttribute((const void*)tgemm2<2>,     cudaFuncAttributeMaxDynamicSharedMemorySize, SM_SINGLE);
    cudaFuncSetAttribute((const void*)tgemm2b<1,1>,  cudaFuncAttributeMaxDynamicSharedMemorySize, SM_BF);
    cudaFuncSetAttribute((const void*)tgemm2b<0,0>,  cudaFuncAttributeMaxDynamicSharedMemorySize, SM_BF);
    cudaFuncSetAttribute((const void*)tgemm2b<1,2>,  cudaFuncAttributeMaxDynamicSharedMemorySize, SM_BF);

    // T0: converts + transposes
    f2bf_k<<<((size_t)VD*FD/4 + 255)/256, 256>>>(E, pEbf, (size_t)VD*FD/4);
    transpose_bf<<<dim3(FD/32, VD/32), dim3(32,8)>>>(E, pEtbf, VD, FD);
    transpose_k<<<dim3(FD/32, FD/32), dim3(32,8)>>>(Wp, pwt1, FD, FD);

    // K1: v = relu(h @ Wh^T + bh + hb)   [fp32 split-K 4: exact relu masks]
    gemm_nt_f32_part<<<dim3(FD/BN, TOK/BM, 4), 256>>>(
        h_, Wh, ppart, TOK, FD, 256, HD, HD, FD);
    reduce_v<<<(TOK*FD + 255)/256, 256>>>(ppart, bh, hb, pv);

    // K2: pre_o = v @ Wp^T + bp          [3xtf32]
    tgemm<1,1><<<dim3(FD/128, TOK/128, 1), 256, SM_SPLIT>>>(
        pv, Wp, ppreo, TOK, FD, FD, FD, FD, FD, bp, nullptr);

    // K3: LN forward (xhat fp32, o bf16)
    ln_fwd<<<TOK, 256>>>(ppreo, pxhat, pobf, prstd, gam, bet);

    // K4: logits = o @ E^T + ob   [bf16, fused row stats]
    tgemm2b<1,1><<<dim3(VD/128, TOK/128, 1), 256, SM_BF>>>(
        pobf, pEbf, plog, TOK, VD, FD, FD, VD, FD, ob, ppmax, ppsum, NTV);

    // K5: combine partials -> rowm, rowiz
    rowstat_fin<<<TOK, 256>>>(ppmax, ppsum, NTV, pm, piz);

    // K5b: P = softmax(logits) -> bf16
    softmax_apply_bf<<<(TOK*(VD/4) + 255)/256, 256>>>(plog, pm, piz, pPbf);

    // K6: do_part = P @ Et^T   [bf16, split-K 4]
    tgemm2b<0,0><<<dim3(FD/128, TOK/128, 4), 256, SM_BF>>>(
        pPbf, pEtbf, ppart, TOK, FD, VD, VD, FD, 8000, nullptr, nullptr, nullptr, 0);

    // K7: fused reduce_do + LN backward -> dpre_o
    ln_bwd_fused<<<TOK, 256>>>(ppart, E, lab, pxhat, prstd, gam, pdo);

    // K8: gbp
    colsum_part<<<dim3(FD/256, 16), 256>>>(pdo, pcs);
    colsum_fin<<<FD/256, 256>>>(pcs, o_gbp);

    // K9: gWp = dpre_o^T @ v   (SIMT fp32 TN split-K 16)
    gemm_tn<<<dim3(FD/BN, FD/BM, 16), 256>>>(pdo, pv, ppart, FD, FD, 128, FD, FD, FD);
    reduce_part16<<<(FD*FD + 255)/256, 256>>>(ppart, o_gWp, FD*FD);

    // T1: gWpT
    transpose_k<<<dim3(FD/32, FD/32), dim3(32,8)>>>(o_gWp, pwt2, FD, FD);

    // K10: dpre_v = (dpre_o @ Wp) * (v>0)   [3xtf32]
    tgemm<3,1><<<dim3(FD/128, TOK/128, 1), 256, SM_SPLIT>>>(
        pdo, pwt1, pdv, TOK, FD, FD, FD, FD, FD, nullptr, pv);

    // K11: gWh = dpre_v^T @ h   (SIMT fp32 TN split-K 16)
    gemm_tn<<<dim3(HD/BN, FD/BM, 16), 256>>>(pdv, h_, ppart, FD, HD, 128, FD, HD, HD);
    reduce_part16<<<(FD*HD + 255)/256, 256>>>(ppart, o_gWh, FD*HD);

    // K12: ghb
    colsum_part<<<dim3(FD/256, 16), 256>>>(pdv, pcs);
    colsum_fin<<<FD/256, 256>>>(pcs, o_ghb);

    // K13: vu = (v @ gWp) * v   [tf32 + fused elementwise mult, into g_do]
    tgemm2<2><<<dim3(FD/128, TOK/128, 1), 256, SM_SINGLE>>>(
        pv, pwt2, pdo, TOK, FD, FD, FD, FD, FD, pv);

    // K14: t = vu @ step_W^T   [tf32]
    tgemm2<0><<<dim3(FD/128, TOK/128, 1), 256, SM_SINGLE>>>(
        pdo, sW, pt, TOK, FD, FD, FD, FD, FD, nullptr);

    // K15: fast pre-LN + LN -> xf (fp32 + bf16)
    fast_ln<<<TOK, 256>>>(ppreo, pv, pt, o_gbp, sb, gam, bet, pxf, pxfbf);

    // K16: fast logits stats only  [bf16, STAT=2]
    tgemm2b<1,2><<<dim3(VD/128, TOK/128, 1), 256, SM_BF>>>(
        pxfbf, pEbf, nullptr, TOK, VD, FD, FD, VD, FD, ob, ppmax, ppsum, NTV);

    // K17: fast loss (fused label logit + stats combine)
    fast_loss_fin<<<TOK, 256>>>(ppmax, ppsum, NTV, pxf, E, ob, lab, o_loss);
}

// round 16
// speedup vs baseline: 1.0901x; 1.0733x over previous
#include <cuda_runtime.h>
#include <cuda_bf16.h>
#include <math.h>
#include <stdint.h>

#define TOK 2048
#define HD  1024
#define FD  512
#define VD  32000
#define NTV (VD/128)   // 250 column tiles for V-GEMMs

// ---------------- scratch (__device__ globals) ----------------
__device__ float g_v    [TOK*FD];
__device__ float g_preo [TOK*FD];
__device__ float g_xhat [TOK*FD];
__device__ float g_rstd [TOK];
__device__ float g_do   [TOK*FD];   // dpre_o, then vu
__device__ float g_dv   [TOK*FD];
__device__ float g_t    [TOK*FD];
__device__ float g_xf   [TOK*FD];
__device__ float g_logits[(size_t)TOK*VD];
__device__ float g_rowm [TOK];
__device__ float g_rowiz[TOK];
__device__ float g_part [16*FD*HD];
__device__ float g_wt1  [FD*FD];
__device__ float g_wt2  [FD*FD];
__device__ float g_csum [16*FD];
__device__ float g_pmax [TOK*NTV];
__device__ float g_psum [TOK*NTV];
__device__ __nv_bfloat16 g_Ebf [(size_t)VD*FD];
__device__ __nv_bfloat16 g_Etbf[(size_t)FD*VD];
__device__ __nv_bfloat16 g_obf [TOK*FD];
__device__ __nv_bfloat16 g_xfbf[TOK*FD];
__device__ __nv_bfloat16 g_Pbf [(size_t)TOK*VD];

__device__ __forceinline__ float to_tf32(float x){
    float y; asm("cvt.rna.tf32.f32 %0, %1;" : "=f"(y) : "f"(x)); return y;
}
__device__ __forceinline__ void cp_async16(void* sdst, const void* gsrc){
    uint32_t s = (uint32_t)__cvta_generic_to_shared(sdst);
    asm volatile("cp.async.cg.shared.global [%0], [%1], 16;" :: "r"(s), "l"(gsrc) : "memory");
}

constexpr int SSTR = 36;
constexpr int ABUF = 128 * SSTR;
constexpr int SM_SINGLE = 4 * ABUF * 4;    // tgemm2 tf32
constexpr int SM_SPLIT  = 8 * ABUF * 4;    // tgemm split
constexpr int WSTR  = 20;
constexpr int ABUFW = 128 * WSTR;
constexpr int SM_BF = 6 * ABUFW * 4;       // 61440 B (3-stage ring: 3xA + 3xB)

// =====================================================================
// tgemm2b: bf16 m16n8k16 GEMM, occ-2, 3-stage cp.async ring,
// ONE __syncthreads per k-tile. C = A @ B^T (f32 accum).
// A [M,K] bf16, B [N,K] bf16. 128x128x32 tiles, 8 warps.
// EPI: 0 none | 1 +b1[col]
// STAT: 0 none | 1 write C + partials | 2 partials only
// =====================================================================
template<int EPI, int STAT>
__global__ void __launch_bounds__(256, 2) tgemm2b(
    const __nv_bfloat16* __restrict__ A, const __nv_bfloat16* __restrict__ B,
    float* __restrict__ C,
    int M, int N, int lda, int ldb, int ldc, int klen,
    const float* __restrict__ b1,
    float* __restrict__ pmax, float* __restrict__ psum, int ntil)
{
    extern __shared__ uint32_t smw[];
    uint32_t* sA = smw;                 // 3 x ABUFW
    uint32_t* sB = smw + 3 * ABUFW;     // 3 x ABUFW

    const int tid  = threadIdx.x;
    const int lane = tid & 31;
    const int wid  = tid >> 5;
    const int wm   = wid & 1;
    const int wn   = wid >> 1;
    const int bm   = blockIdx.y * 128;
    const int bn   = blockIdx.x * 128;
    const int kbeg = blockIdx.z * klen;

    int crow[2], cc[2];
#pragma unroll
    for (int i = 0; i < 2; i++) {
        int idx = i * 256 + tid;
        crow[i] = idx >> 2;
        cc[i]   = idx & 3;
    }

    float c[4][4][4];
#pragma unroll
    for (int mi = 0; mi < 4; mi++)
#pragma unroll
        for (int ni = 0; ni < 4; ni++)
#pragma unroll
            for (int j = 0; j < 4; j++) c[mi][ni][j] = 0.f;

    auto issue = [&](int kt, int buf) {
#pragma unroll
        for (int i = 0; i < 2; i++) {
            const int kk = kbeg + kt + cc[i] * 8;
            cp_async16(sA + buf * ABUFW + crow[i] * WSTR + cc[i] * 4,
                       A + (size_t)(bm + crow[i]) * lda + kk);
            cp_async16(sB + buf * ABUFW + crow[i] * WSTR + cc[i] * 4,
                       B + (size_t)(bn + crow[i]) * ldb + kk);
        }
        asm volatile("cp.async.commit_group;" ::: "memory");
    };

    const int q    = lane & 3;
    const int aoff = (wm * 64 + (lane >> 2)) * WSTR + q;
    const int boff = (wn * 32 + (lane >> 2)) * WSTR + q;

    auto compute = [&](int buf) {
#pragma unroll
        for (int ks = 0; ks < 2; ks++) {
            const int k0 = ks * 8;
            uint32_t af[4][4], bf[4][2];
#pragma unroll
            for (int mi = 0; mi < 4; mi++) {
                const uint32_t* ap = sA + buf * ABUFW + aoff + mi * 16 * WSTR + k0;
                af[mi][0] = ap[0];
                af[mi][1] = ap[8 * WSTR];
                af[mi][2] = ap[4];
                af[mi][3] = ap[8 * WSTR + 4];
            }
#pragma unroll
            for (int ni = 0; ni < 4; ni++) {
                const uint32_t* bp = sB + buf * ABUFW + boff + ni * 8 * WSTR + k0;
                bf[ni][0] = bp[0];
                bf[ni][1] = bp[4];
            }
#pragma unroll
            for (int mi = 0; mi < 4; mi++)
#pragma unroll
                for (int ni = 0; ni < 4; ni++) {
                    asm volatile(
                        "mma.sync.aligned.m16n8k16.row.col.f32.bf16.bf16.f32 "
                        "{%0,%1,%2,%3}, {%4,%5,%6,%7}, {%8,%9}, {%0,%1,%2,%3};"
                        : "+f"(c[mi][ni][0]), "+f"(c[mi][ni][1]),
                          "+f"(c[mi][ni][2]), "+f"(c[mi][ni][3])
                        : "r"(af[mi][0]), "r"(af[mi][1]), "r"(af[mi][2]), "r"(af[mi][3]),
                          "r"(bf[ni][0]), "r"(bf[ni][1]));
                }
        }
    };

    // 3-stage ring pipeline, one barrier per tile.
    issue(0, 0);
    if (32 < klen) issue(32, 1);
    int t = 0;
    for (int kt = 0; kt < klen; kt += 32, t++) {
        if (kt + 32 < klen) {
            asm volatile("cp.async.wait_group 1;" ::: "memory");
        } else {
            asm volatile("cp.async.wait_group 0;" ::: "memory");
        }
        __syncthreads();
        compute(t % 3);
        if (kt + 64 < klen) issue(kt + 64, (t + 2) % 3);
    }

    if (EPI == 1) {
#pragma unroll
        for (int mi = 0; mi < 4; mi++)
#pragma unroll
            for (int ni = 0; ni < 4; ni++) {
                const int col = bn + wn * 32 + ni * 8 + (lane & 3) * 2;
                float bb0 = b1[col], bb1 = b1[col + 1];
                c[mi][ni][0] += bb0; c[mi][ni][1] += bb1;
                c[mi][ni][2] += bb0; c[mi][ni][3] += bb1;
            }
    }

    if (STAT != 2) {
        float* Cp = C + (size_t)blockIdx.z * M * N;
#pragma unroll
        for (int mi = 0; mi < 4; mi++) {
            const int r0 = bm + wm * 64 + mi * 16 + (lane >> 2);
#pragma unroll
            for (int ni = 0; ni < 4; ni++) {
                const int col = bn + wn * 32 + ni * 8 + (lane & 3) * 2;
#pragma unroll
                for (int h = 0; h < 2; h++) {
                    float2 o = {c[mi][ni][h * 2], c[mi][ni][h * 2 + 1]};
                    *(float2*)(Cp + (size_t)(r0 + h * 8) * ldc + col) = o;
                }
            }
        }
    }

    if (STAT) {
        float* smax = (float*)smw;
        float* ssum = (float*)smw + 512;
        __syncthreads();
#pragma unroll
        for (int mi = 0; mi < 4; mi++)
#pragma unroll
            for (int h = 0; h < 2; h++) {
                float m = -1e30f, s = 0.f;
#pragma unroll
                for (int ni = 0; ni < 4; ni++)
#pragma unroll
                    for (int j = 0; j < 2; j++) {
                        float x = c[mi][ni][h * 2 + j];
                        float mn = fmaxf(m, x);
                        s = s * __expf(m - mn) + __expf(x - mn);
                        m = mn;
                    }
#pragma unroll
                for (int o = 1; o <= 2; o <<= 1) {
                    float m2 = __shfl_xor_sync(0xffffffff, m, o);
                    float s2 = __shfl_xor_sync(0xffffffff, s, o);
                    float mo = fmaxf(m, m2);
                    s = s * __expf(m - mo) + s2 * __expf(m2 - mo);
                    m = mo;
                }
                if ((lane & 3) == 0) {
                    int rl = wm * 64 + mi * 16 + (lane >> 2) + h * 8;
                    smax[wn * 128 + rl] = m;
                    ssum[wn * 128 + rl] = s;
                }
            }
        __syncthreads();
        if (tid < 128) {
            float m = smax[tid], s = ssum[tid];
#pragma unroll
            for (int w = 1; w < 4; w++) {
                float m2 = smax[w * 128 + tid], s2 = ssum[w * 128 + tid];
                float mo = fmaxf(m, m2);
                s = s * __expf(m - mo) + s2 * __expf(m2 - mo);
                m = mo;
            }
            pmax[(size_t)(bm + tid) * ntil + blockIdx.x] = m;
            psum[(size_t)(bm + tid) * ntil + blockIdx.x] = s;
        }
    }
}

// =====================================================================
// tgemm2: occ-2 single-tf32 GEMM (K13/K14)
// EPI: 0 none | 2 multiply elementwise by m1[row*ldc+col] (vu fusion)
// =====================================================================
template<int EPI>
__global__ void __launch_bounds__(256, 2) tgemm2(
    const float* __restrict__ A, const float* __restrict__ B, float* __restrict__ C,
    int M, int N, int lda, int ldb, int ldc, int klen,
    const float* __restrict__ m1)
{
    extern __shared__ float sm[];
    float* sA = sm;
    float* sB = sm + 2 * ABUF;

    const int tid  = threadIdx.x;
    const int lane = tid & 31;
    const int wid  = tid >> 5;
    const int wm   = wid & 1;
    const int wn   = wid >> 1;
    const int bm   = blockIdx.y * 128;
    const int bn   = blockIdx.x * 128;
    const int kbeg = blockIdx.z * klen;

    int lrow[4], lq[4];
#pragma unroll
    for (int i = 0; i < 4; i++) {
        int idx = i * 256 + tid;
        lrow[i] = idx >> 3;
        lq[i]   = (idx & 7) * 4;
    }

    float c[4][4][4];
#pragma unroll
    for (int mi = 0; mi < 4; mi++)
#pragma unroll
        for (int ni = 0; ni < 4; ni++)
#pragma unroll
            for (int j = 0; j < 4; j++) c[mi][ni][j] = 0.f;

    auto issue = [&](int kt, int buf) {
#pragma unroll
        for (int i = 0; i < 4; i++) {
            const int kk = kbeg + kt + lq[i];
            const int off = buf * ABUF + lrow[i] * SSTR + lq[i];
            cp_async16(sA + off, A + (size_t)(bm + lrow[i]) * lda + kk);
            cp_async16(sB + off, B + (size_t)(bn + lrow[i]) * ldb + kk);
        }
        asm volatile("cp.async.commit_group;" ::: "memory");
    };

    const int aoff = (wm * 64 + (lane >> 2)) * SSTR + (lane & 3);
    const int boff = (wn * 32 + (lane >> 2)) * SSTR + (lane & 3);

    auto compute = [&](int buf) {
#pragma unroll
        for (int ks = 0; ks < 4; ks++) {
            const int k0 = ks * 8;
            uint32_t af[4][4], bf[4][2];
#pragma unroll
            for (int mi = 0; mi < 4; mi++) {
                const float* ap = sA + buf * ABUF + aoff + mi * 16 * SSTR + k0;
                af[mi][0] = __float_as_uint(ap[0]);
                af[mi][1] = __float_as_uint(ap[8 * SSTR]);
                af[mi][2] = __float_as_uint(ap[4]);
                af[mi][3] = __float_as_uint(ap[8 * SSTR + 4]);
            }
#pragma unroll
            for (int ni = 0; ni < 4; ni++) {
                const float* bp = sB + buf * ABUF + boff + ni * 8 * SSTR + k0;
                bf[ni][0] = __float_as_uint(bp[0]);
                bf[ni][1] = __float_as_uint(bp[4]);
            }
#pragma unroll
            for (int mi = 0; mi < 4; mi++)
#pragma unroll
                for (int ni = 0; ni < 4; ni++) {
                    asm volatile(
                        "mma.sync.aligned.m16n8k8.row.col.f32.tf32.tf32.f32 "
                        "{%0,%1,%2,%3}, {%4,%5,%6,%7}, {%8,%9}, {%0,%1,%2,%3};"
                        : "+f"(c[mi][ni][0]), "+f"(c[mi][ni][1]),
                          "+f"(c[mi][ni][2]), "+f"(c[mi][ni][3])
                        : "r"(af[mi][0]), "r"(af[mi][1]), "r"(af[mi][2]), "r"(af[mi][3]),
                          "r"(bf[ni][0]), "r"(bf[ni][1]));
                }
        }
    };

    issue(0, 0);
    int buf = 0;
    for (int kt = 0; kt < klen; kt += 32) {
        const bool nxt = (kt + 32) < klen;
        if (nxt) {
            issue(kt + 32, buf ^ 1);
            asm volatile("cp.async.wait_group 1;" ::: "memory");
        } else {
            asm volatile("cp.async.wait_group 0;" ::: "memory");
        }
        __syncthreads();
        compute(buf);
        __syncthreads();
        buf ^= 1;
    }

    float* Cp = C;
#pragma unroll
    for (int mi = 0; mi < 4; mi++) {
        const int r0 = bm + wm * 64 + mi * 16 + (lane >> 2);
#pragma unroll
        for (int ni = 0; ni < 4; ni++) {
            const int col = bn + wn * 32 + ni * 8 + (lane & 3) * 2;
#pragma unroll
            for (int h = 0; h < 2; h++) {
                const int row = r0 + h * 8;
                float v0 = c[mi][ni][h * 2], v1 = c[mi][ni][h * 2 + 1];
                if (EPI == 2) {
                    const float* mp = m1 + (size_t)row * ldc + col;
                    v0 *= mp[0];
                    v1 *= mp[1];
                }
                float2 o = {v0, v1};
                *(float2*)(Cp + (size_t)row * ldc + col) = o;
            }
        }
    }
}

// =====================================================================
// 3xtf32 split GEMM (K2, K10)
// =====================================================================
template<int EPI, int SPLIT>
__global__ void __launch_bounds__(256) tgemm(
    const float* __restrict__ A, const float* __restrict__ B, float* __restrict__ C,
    int M, int N, int lda, int ldb, int ldc, int klen,
    const float* __restrict__ b1, const float* __restrict__ mask)
{
    extern __shared__ float sm[];
    float* sAhi = sm;
    float* sBhi = sm + 2 * ABUF;
    float* sAlo = sm + 4 * ABUF;
    float* sBlo = sm + 6 * ABUF;

    const int tid  = threadIdx.x;
    const int lane = tid & 31;
    const int wid  = tid >> 5;
    const int wm   = wid & 1;
    const int wn   = wid >> 1;
    const int bm   = blockIdx.y * 128;
    const int bn   = blockIdx.x * 128;
    const int kbeg = blockIdx.z * klen;

    int lrow[4], lq[4];
#pragma unroll
    for (int i = 0; i < 4; i++) {
        int idx = i * 256 + tid;
        lrow[i] = idx >> 3;
        lq[i]   = (idx & 7) * 4;
    }

    float c[4][4][4];
#pragma unroll
    for (int mi = 0; mi < 4; mi++)
#pragma unroll
        for (int ni = 0; ni < 4; ni++)
#pragma unroll
            for (int j = 0; j < 4; j++) c[mi][ni][j] = 0.f;

    float4 rA[4], rB[4];

    auto load_tile = [&](int kt) {
#pragma unroll
        for (int i = 0; i < 4; i++) {
            int kk = kbeg + kt + lq[i];
            rA[i] = *(const float4*)(A + (size_t)(bm + lrow[i]) * lda + kk);
            rB[i] = *(const float4*)(B + (size_t)(bn + lrow[i]) * ldb + kk);
        }
    };

    auto store_tile = [&](int buf) {
#pragma unroll
        for (int i = 0; i < 4; i++) {
            float4 a = rA[i], b = rB[i];
            float4 ah, bh;
            ah.x = to_tf32(a.x); ah.y = to_tf32(a.y); ah.z = to_tf32(a.z); ah.w = to_tf32(a.w);
            bh.x = to_tf32(b.x); bh.y = to_tf32(b.y); bh.z = to_tf32(b.z); bh.w = to_tf32(b.w);
            const int off = lrow[i] * SSTR + lq[i];
            *(float4*)(sAhi + buf * ABUF + off) = ah;
            *(float4*)(sBhi + buf * ABUF + off) = bh;
            if (SPLIT) {
                float4 al, bl;
                al.x = to_tf32(a.x - ah.x); al.y = to_tf32(a.y - ah.y);
                al.z = to_tf32(a.z - ah.z); al.w = to_tf32(a.w - ah.w);
                bl.x = to_tf32(b.x - bh.x); bl.y = to_tf32(b.y - bh.y);
                bl.z = to_tf32(b.z - bh.z); bl.w = to_tf32(b.w - bh.w);
                *(float4*)(sAlo + buf * ABUF + off) = al;
                *(float4*)(sBlo + buf * ABUF + off) = bl;
            }
        }
    };

    const int aoff = (wm * 64 + (lane >> 2)) * SSTR + (lane & 3);
    const int boff = (wn * 32 + (lane >> 2)) * SSTR + (lane & 3);

    auto compute = [&](int buf) {
#pragma unroll
        for (int ks = 0; ks < 4; ks++) {
            const int k0 = ks * 8;
            uint32_t afh[4][4], bfh[4][2];
            uint32_t afl[4][4], bfl[4][2];
#pragma unroll
            for (int mi = 0; mi < 4; mi++) {
                const float* ap = sAhi + buf * ABUF + aoff + mi * 16 * SSTR + k0;
                afh[mi][0] = __float_as_uint(ap[0]);
                afh[mi][1] = __float_as_uint(ap[8 * SSTR]);
                afh[mi][2] = __float_as_uint(ap[4]);
                afh[mi][3] = __float_as_uint(ap[8 * SSTR + 4]);
                if (SPLIT) {
                    const float* al = sAlo + buf * ABUF + aoff + mi * 16 * SSTR + k0;
                    afl[mi][0] = __float_as_uint(al[0]);
                    afl[mi][1] = __float_as_uint(al[8 * SSTR]);
                    afl[mi][2] = __float_as_uint(al[4]);
                    afl[mi][3] = __float_as_uint(al[8 * SSTR + 4]);
                }
            }
#pragma unroll
            for (int ni = 0; ni < 4; ni++) {
                const float* bp = sBhi + buf * ABUF + boff + ni * 8 * SSTR + k0;
                bfh[ni][0] = __float_as_uint(bp[0]);
                bfh[ni][1] = __float_as_uint(bp[4]);
                if (SPLIT) {
                    const float* bl = sBlo + buf * ABUF + boff + ni * 8 * SSTR + k0;
                    bfl[ni][0] = __float_as_uint(bl[0]);
                    bfl[ni][1] = __float_as_uint(bl[4]);
                }
            }
#pragma unroll
            for (int mi = 0; mi < 4; mi++)
#pragma unroll
                for (int ni = 0; ni < 4; ni++) {
                    if (SPLIT) {
                        asm volatile(
                            "mma.sync.aligned.m16n8k8.row.col.f32.tf32.tf32.f32 "
                            "{%0,%1,%2,%3}, {%4,%5,%6,%7}, {%8,%9}, {%0,%1,%2,%3};"
                            : "+f"(c[mi][ni][0]), "+f"(c[mi][ni][1]),
                              "+f"(c[mi][ni][2]), "+f"(c[mi][ni][3])
                            : "r"(afl[mi][0]), "r"(afl[mi][1]), "r"(afl[mi][2]), "r"(afl[mi][3]),
                              "r"(bfh[ni][0]), "r"(bfh[ni][1]));
                        asm volatile(
                            "mma.sync.aligned.m16n8k8.row.col.f32.tf32.tf32.f32 "
                            "{%0,%1,%2,%3}, {%4,%5,%6,%7}, {%8,%9}, {%0,%1,%2,%3};"
                            : "+f"(c[mi][ni][0]), "+f"(c[mi][ni][1]),
                              "+f"(c[mi][ni][2]), "+f"(c[mi][ni][3])
                            : "r"(afh[mi][0]), "r"(afh[mi][1]), "r"(afh[mi][2]), "r"(afh[mi][3]),
                              "r"(bfl[ni][0]), "r"(bfl[ni][1]));
                    }
                    asm volatile(
                        "mma.sync.aligned.m16n8k8.row.col.f32.tf32.tf32.f32 "
                        "{%0,%1,%2,%3}, {%4,%5,%6,%7}, {%8,%9}, {%0,%1,%2,%3};"
                        : "+f"(c[mi][ni][0]), "+f"(c[mi][ni][1]),
                          "+f"(c[mi][ni][2]), "+f"(c[mi][ni][3])
                        : "r"(afh[mi][0]), "r"(afh[mi][1]), "r"(afh[mi][2]), "r"(afh[mi][3]),
                          "r"(bfh[ni][0]), "r"(bfh[ni][1]));
                }
        }
    };

    load_tile(0);
    store_tile(0);
    __syncthreads();
    int buf = 0;
    for (int kt = 0; kt < klen; kt += 32) {
        const bool nxt = (kt + 32) < klen;
        if (nxt) load_tile(kt + 32);
        compute(buf);
        if (nxt) store_tile(buf ^ 1);
        __syncthreads();
        buf ^= 1;
    }

    float* Cp = C + (size_t)blockIdx.z * M * N;
#pragma unroll
    for (int mi = 0; mi < 4; mi++) {
        const int r0 = bm + wm * 64 + mi * 16 + (lane >> 2);
#pragma unroll
        for (int ni = 0; ni < 4; ni++) {
            const int col = bn + wn * 32 + ni * 8 + (lane & 3) * 2;
#pragma unroll
            for (int h = 0; h < 2; h++) {
                const int row = r0 + h * 8;
                float v0 = c[mi][ni][h * 2], v1 = c[mi][ni][h * 2 + 1];
                if (EPI == 1) { v0 += b1[col]; v1 += b1[col + 1]; }
                if (EPI == 3) {
                    const float* mp = mask + (size_t)row * ldc + col;
                    v0 = (mp[0] > 0.f) ? v0 : 0.f;
                    v1 = (mp[1] > 0.f) ? v1 : 0.f;
                }
                float2 o = {v0, v1};
                *(float2*)(Cp + (size_t)row * ldc + col) = o;
            }
        }
    }
}

// =====================================================================
// fp32 SIMT NT GEMM, split-K partials (K1)
// =====================================================================
constexpr int BM = 128, BN = 128, BK = 8, PADX = 4;

__global__ void __launch_bounds__(256) gemm_nt_f32_part(
    const float* __restrict__ A, const float* __restrict__ B, float* __restrict__ C,
    int M, int N, int klen, int lda, int ldb, int ldc)
{
    __shared__ __align__(16) float As[BK][BM + PADX];
    __shared__ __align__(16) float Bs[BK][BN + PADX];
    const int tid = threadIdx.x;
    const int tx = tid & 15, ty = tid >> 4;
    const int bm = blockIdx.y * BM, bn = blockIdx.x * BN;
    const int kbeg = blockIdx.z * klen;

    float acc[8][8];
#pragma unroll
    for (int i = 0; i < 8; i++)
#pragma unroll
        for (int j = 0; j < 8; j++) acc[i][j] = 0.f;

    for (int kt = 0; kt < klen; kt += BK) {
        {
            const int mm = tid >> 1;
            const int kq = (tid & 1) * 4;
            float4 av = *(const float4*)(A + (size_t)(bm + mm) * lda + (kbeg + kt + kq));
            As[kq + 0][mm] = av.x; As[kq + 1][mm] = av.y;
            As[kq + 2][mm] = av.z; As[kq + 3][mm] = av.w;
            float4 bv = *(const float4*)(B + (size_t)(bn + mm) * ldb + (kbeg + kt + kq));
            Bs[kq + 0][mm] = bv.x; Bs[kq + 1][mm] = bv.y;
            Bs[kq + 2][mm] = bv.z; Bs[kq + 3][mm] = bv.w;
        }
        __syncthreads();
#pragma unroll
        for (int kk = 0; kk < BK; kk++) {
            float4 a0 = *(float4*)&As[kk][ty * 8];
            float4 a1 = *(float4*)&As[kk][ty * 8 + 4];
            float4 b0 = *(float4*)&Bs[kk][tx * 8];
            float4 b1v = *(float4*)&Bs[kk][tx * 8 + 4];
            float a[8] = {a0.x, a0.y, a0.z, a0.w, a1.x, a1.y, a1.z, a1.w};
            float b[8] = {b0.x, b0.y, b0.z, b0.w, b1v.x, b1v.y, b1v.z, b1v.w};
#pragma unroll
            for (int i = 0; i < 8; i++)
#pragma unroll
                for (int j = 0; j < 8; j++) acc[i][j] += a[i] * b[j];
        }
        __syncthreads();
    }
    float* Cp = C + (size_t)blockIdx.z * M * N;
#pragma unroll
    for (int i = 0; i < 8; i++) {
        const int row = bm + ty * 8 + i;
#pragma unroll
        for (int jq = 0; jq < 8; jq += 4) {
            const int col = bn + tx * 8 + jq;
            float4 o = {acc[i][jq], acc[i][jq + 1], acc[i][jq + 2], acc[i][jq + 3]};
            *(float4*)(Cp + (size_t)row * ldc + col) = o;
        }
    }
}

__global__ void reduce_v(const float* __restrict__ part, const float* __restrict__ b1,
                         const float* __restrict__ b2, float* __restrict__ out)
{
    const int i = blockIdx.x * blockDim.x + threadIdx.x;
    if (i >= TOK * FD) return;
    float s = 0.f;
#pragma unroll
    for (int k = 0; k < 4; k++) s += part[(size_t)k * TOK * FD + i];
    const int col = i & 511;
    s += b1[col] + b2[col];
    out[i] = s > 0.f ? s : 0.f;
}

// =====================================================================
// transposes / converts
// =====================================================================
__global__ void transpose_k(const float* __restrict__ src, float* __restrict__ dst,
                            int R, int C)
{
    __shared__ float t[32][33];
    const int c0 = blockIdx.x * 32, r0 = blockIdx.y * 32;
#pragma unroll
    for (int i = threadIdx.y; i < 32; i += 8)
        t[i][threadIdx.x] = src[(size_t)(r0 + i) * C + (c0 + threadIdx.x)];
    __syncthreads();
#pragma unroll
    for (int i = threadIdx.y; i < 32; i += 8)
        dst[(size_t)(c0 + i) * R + (r0 + threadIdx.x)] = t[threadIdx.x][i];
}

__global__ void transpose_bf(const float* __restrict__ src, __nv_bfloat16* __restrict__ dst,
                             int R, int C)
{
    __shared__ float t[32][33];
    const int c0 = blockIdx.x * 32, r0 = blockIdx.y * 32;
#pragma unroll
    for (int i = threadIdx.y; i < 32; i += 8)
        t[i][threadIdx.x] = src[(size_t)(r0 + i) * C + (c0 + threadIdx.x)];
    __syncthreads();
#pragma unroll
    for (int i = threadIdx.y; i < 32; i += 8)
        dst[(size_t)(c0 + i) * R + (r0 + threadIdx.x)] = __float2bfloat16(t[threadIdx.x][i]);
}

__global__ void f2bf_k(const float* __restrict__ in, __nv_bfloat16* __restrict__ out, size_t n4)
{
    const size_t i = (size_t)blockIdx.x * blockDim.x + threadIdx.x;
    if (i >= n4) return;
    float4 x = *((const float4*)in + i);
    __nv_bfloat162 lo = __floats2bfloat162_rn(x.x, x.y);
    __nv_bfloat162 hi = __floats2bfloat162_rn(x.z, x.w);
    *((__nv_bfloat162*)out + i * 2)     = lo;
    *((__nv_bfloat162*)out + i * 2 + 1) = hi;
}

// =====================================================================
// SIMT TN GEMM
// =====================================================================
__global__ void __launch_bounds__(256) gemm_tn(
    const float* __restrict__ A, const float* __restrict__ B, float* __restrict__ C,
    int M, int N, int klen, int lda, int ldb, int ldc)
{
    __shared__ __align__(16) float As[BK][BM + PADX];
    __shared__ __align__(16) float Bs[BK][BN + PADX];
    const int tid = threadIdx.x;
    const int tx = tid & 15, ty = tid >> 4;
    const int bm = blockIdx.y * BM, bn = blockIdx.x * BN;
    const int kbeg = blockIdx.z * klen;

    float acc[8][8];
#pragma unroll
    for (int i = 0; i < 8; i++)
#pragma unroll
        for (int j = 0; j < 8; j++) acc[i][j] = 0.f;

    for (int kt = 0; kt < klen; kt += BK) {
        {
            const int kk = tid >> 5, mq = (tid & 31) * 4;
            *(float4*)&As[kk][mq] = *(const float4*)(A + (size_t)(kbeg + kt + kk) * lda + bm + mq);
            *(float4*)&Bs[kk][mq] = *(const float4*)(B + (size_t)(kbeg + kt + kk) * ldb + bn + mq);
        }
        __syncthreads();
#pragma unroll
        for (int kk = 0; kk < BK; kk++) {
            float4 a0 = *(float4*)&As[kk][ty * 8];
            float4 a1 = *(float4*)&As[kk][ty * 8 + 4];
            float4 b0 = *(float4*)&Bs[kk][tx * 8];
            float4 b1v = *(float4*)&Bs[kk][tx * 8 + 4];
            float a[8] = {a0.x, a0.y, a0.z, a0.w, a1.x, a1.y, a1.z, a1.w};
            float b[8] = {b0.x, b0.y, b0.z, b0.w, b1v.x, b1v.y, b1v.z, b1v.w};
#pragma unroll
            for (int i = 0; i < 8; i++)
#pragma unroll
                for (int j = 0; j < 8; j++) acc[i][j] += a[i] * b[j];
        }
        __syncthreads();
    }
    float* Cp = C + (size_t)blockIdx.z * M * N;
#pragma unroll
    for (int i = 0; i < 8; i++) {
        const int rr = bm + ty * 8 + i;
#pragma unroll
        for (int jq = 0; jq < 8; jq += 4) {
            const int cc = bn + tx * 8 + jq;
            float4 o = {acc[i][jq], acc[i][jq + 1], acc[i][jq + 2], acc[i][jq + 3]};
            *(float4*)(Cp + (size_t)rr * ldc + cc) = o;
        }
    }
}

// ---------------- LayerNorm forward (writes xhat fp32 + o bf16) ----------------
__global__ void ln_fwd(const float* __restrict__ x, float* __restrict__ xhat,
                       __nv_bfloat16* __restrict__ obf, float* __restrict__ rstd,
                       const float* __restrict__ gam, const float* __restrict__ bet)
{
    const int row = blockIdx.x, tid = threadIdx.x;
    const size_t base = (size_t)row * FD;
    float x0 = x[base + tid], x1 = x[base + tid + 256];
    __shared__ float r1[256], r2[256];
    r1[tid] = x0 + x1;
    r2[tid] = x0 * x0 + x1 * x1;
    __syncthreads();
    for (int s = 128; s > 0; s >>= 1) {
        if (tid < s) { r1[tid] += r1[tid + s]; r2[tid] += r2[tid + s]; }
        __syncthreads();
    }
    float mu  = r1[0] * (1.f / FD);
    float var = r2[0] * (1.f / FD) - mu * mu;
    float rs  = rsqrtf(var + 1e-5f);
    if (tid == 0) rstd[row] = rs;
    float h0 = (x0 - mu) * rs, h1 = (x1 - mu) * rs;
    xhat[base + tid]       = h0;
    xhat[base + tid + 256] = h1;
    obf[base + tid]       = __float2bfloat16(h0 * gam[tid]       + bet[tid]);
    obf[base + tid + 256] = __float2bfloat16(h1 * gam[tid + 256] + bet[tid + 256]);
}

// ---------------- fused: do = sum4(part) - E[lab] ; LN backward -> dio ----------------
__global__ void ln_bwd_fused(const float* __restrict__ part, const float* __restrict__ E,
                             const int* __restrict__ lab,
                             const float* __restrict__ xhat, const float* __restrict__ rstd,
                             const float* __restrict__ gamma, float* __restrict__ dio)
{
    const int row = blockIdx.x, tid = threadIdx.x;
    const size_t base = (size_t)row * FD;
    const int l = lab[row];
    float d0 = 0.f, d1 = 0.f;
#pragma unroll
    for (int k = 0; k < 4; k++) {
        d0 += part[(size_t)k * TOK * FD + base + tid];
        d1 += part[(size_t)k * TOK * FD + base + tid + 256];
    }
    d0 -= E[(size_t)l * FD + tid];
    d1 -= E[(size_t)l * FD + tid + 256];
    float h0 = xhat[base + tid], h1 = xhat[base + tid + 256];
    float dx0 = d0 * gamma[tid], dx1 = d1 * gamma[tid + 256];
    __shared__ float r1[256], r2[256];
    r1[tid] = dx0 + dx1;
    r2[tid] = dx0 * h0 + dx1 * h1;
    __syncthreads();
    for (int s = 128; s > 0; s >>= 1) {
        if (tid < s) { r1[tid] += r1[tid + s]; r2[tid] += r2[tid + s]; }
        __syncthreads();
    }
    float m1 = r1[0] * (1.f / FD);
    float m2 = r2[0] * (1.f / FD);
    float rs = rstd[row];
    dio[base + tid]       = rs * (dx0 - m1 - h0 * m2);
    dio[base + tid + 256] = rs * (dx1 - m1 - h1 * m2);
}

// ---------------- fast path pre-LN + LN (fp32 + bf16 out) ----------------
__global__ void fast_ln(const float* __restrict__ preo, const float* __restrict__ v,
                        const float* __restrict__ t, const float* __restrict__ gbp,
                        const float* __restrict__ step_b,
                        const float* __restrict__ gam, const float* __restrict__ bet,
                        float* __restrict__ xfo, __nv_bfloat16* __restrict__ xfbf)
{
    const int row = blockIdx.x, tid = threadIdx.x;
    const size_t base = (size_t)row * FD;
    float v0 = v[base + tid], v1 = v[base + tid + 256];
    __shared__ float r1[256], r2[256];
    r1[tid] = v0 * gbp[tid] + v1 * gbp[tid + 256];
    __syncthreads();
    for (int s = 128; s > 0; s >>= 1) {
        if (tid < s) r1[tid] += r1[tid + s];
        __syncthreads();
    }
    float sb = r1[0];
    __syncthreads();
    float x0 = preo[base + tid]       - v0 * t[base + tid]       - step_b[tid]       * v0 * sb;
    float x1 = preo[base + tid + 256] - v1 * t[base + tid + 256] - step_b[tid + 256] * v1 * sb;
    r1[tid] = x0 + x1;
    r2[tid] = x0 * x0 + x1 * x1;
    __syncthreads();
    for (int s = 128; s > 0; s >>= 1) {
        if (tid < s) { r1[tid] += r1[tid + s]; r2[tid] += r2[tid + s]; }
        __syncthreads();
    }
    float mu  = r1[0] * (1.f / FD);
    float var = r2[0] * (1.f / FD) - mu * mu;
    float rs  = rsqrtf(var + 1e-5f);
    float y0 = ((x0 - mu) * rs) * gam[tid]       + bet[tid];
    float y1 = ((x1 - mu) * rs) * gam[tid + 256] + bet[tid + 256];
    xfo[base + tid]        = y0;
    xfo[base + tid + 256]  = y1;
    xfbf[base + tid]       = __float2bfloat16(y0);
    xfbf[base + tid + 256] = __float2bfloat16(y1);
}

// ---------------- P(bf16) = exp(L - m[row]) * iz[row] ----------------
__global__ void softmax_apply_bf(const float* __restrict__ L, const float* __restrict__ rowm,
                                 const float* __restrict__ rowiz,
                                 __nv_bfloat16* __restrict__ P)
{
    const size_t i = (size_t)blockIdx.x * blockDim.x + threadIdx.x;
    if (i >= (size_t)TOK * VD / 4) return;
    const int row = (int)(i / (VD / 4));
    const float m = rowm[row], iz = rowiz[row];
    float4 x = *((const float4*)L + i);
    x.x = __expf(x.x - m) * iz;
    x.y = __expf(x.y - m) * iz;
    x.z = __expf(x.z - m) * iz;
    x.w = __expf(x.w - m) * iz;
    *((__nv_bfloat162*)P + i * 2)     = __floats2bfloat162_rn(x.x, x.y);
    *((__nv_bfloat162*)P + i * 2 + 1) = __floats2bfloat162_rn(x.z, x.w);
}

// ---------------- combine row-stat partials (softmax stats) ----------------
__global__ void rowstat_fin(const float* __restrict__ pmax, const float* __restrict__ psum,
                            int nt, float* __restrict__ out1, float* __restrict__ out2)
{
    const int row = blockIdx.x, tid = threadIdx.x;
    const float* pm = pmax + (size_t)row * nt;
    const float* ps = psum + (size_t)row * nt;
    float m = -1e30f, s = 0.f;
    for (int i = tid; i < nt; i += 256) {
        float m2 = pm[i], s2 = ps[i];
        float mo = fmaxf(m, m2);
        s = s * __expf(m - mo) + s2 * __expf(m2 - mo);
        m = mo;
    }
    __shared__ float sm_[256], sz_[256];
    sm_[tid] = m; sz_[tid] = s;
    __syncthreads();
    for (int st = 128; st > 0; st >>= 1) {
        if (tid < st) {
            float m2 = sm_[tid + st], s2 = sz_[tid + st];
            float mo = fmaxf(sm_[tid], m2);
            sz_[tid] = sz_[tid] * __expf(sm_[tid] - mo) + s2 * __expf(m2 - mo);
            sm_[tid] = mo;
        }
        __syncthreads();
    }
    if (tid == 0) { out1[row] = sm_[0]; out2[row] = 1.f / sz_[0]; }
}

// ---------------- fused fast loss: stats combine + exact fp32 label logit ----------------
__global__ void fast_loss_fin(const float* __restrict__ pmax, const float* __restrict__ psum,
                              int nt, const float* __restrict__ xf,
                              const float* __restrict__ E, const float* __restrict__ ob,
                              const int* __restrict__ lab, float* __restrict__ out)
{
    const int row = blockIdx.x, tid = threadIdx.x;
    const int l = lab[row];
    __shared__ float sm_[256], sz_[256];

    {
        const size_t base = (size_t)row * FD;
        float p = xf[base + tid] * E[(size_t)l * FD + tid]
                + xf[base + tid + 256] * E[(size_t)l * FD + tid + 256];
        sm_[tid] = p;
        __syncthreads();
        for (int st = 128; st > 0; st >>= 1) {
            if (tid < st) sm_[tid] += sm_[tid + st];
            __syncthreads();
        }
    }
    __shared__ float lablog;
    if (tid == 0) lablog = sm_[0] + ob[l];
    __syncthreads();

    const float* pm = pmax + (size_t)row * nt;
    const float* ps = psum + (size_t)row * nt;
    float m = -1e30f, s = 0.f;
    for (int i = tid; i < nt; i += 256) {
        float m2 = pm[i], s2 = ps[i];
        float mo = fmaxf(m, m2);
        s = s * __expf(m - mo) + s2 * __expf(m2 - mo);
        m = mo;
    }
    sm_[tid] = m; sz_[tid] = s;
    __syncthreads();
    for (int st = 128; st > 0; st >>= 1) {
        if (tid < st) {
            float m2 = sm_[tid + st], s2 = sz_[tid + st];
            float mo = fmaxf(sm_[tid], m2);
            sz_[tid] = sz_[tid] * __expf(sm_[tid] - mo) + s2 * __expf(m2 - mo);
            sm_[tid] = mo;
        }
        __syncthreads();
    }
    if (tid == 0) out[row] = sm_[0] + logf(sz_[0]) - lablog;
}

// ---------------- column sums ----------------
__global__ void colsum_part(const float* __restrict__ X, float* __restrict__ part)
{
    const int col = blockIdx.x * 256 + threadIdx.x;
    const int rc  = blockIdx.y;
    float s = 0.f;
    const int r0 = rc * 128;
#pragma unroll 4
    for (int b = 0; b < 128; b++) s += X[(size_t)(r0 + b) * FD + col];
    part[rc * FD + col] = s;
}
__global__ void colsum_fin(const float* __restrict__ part, float* __restrict__ out)
{
    const int col = blockIdx.x * 256 + threadIdx.x;
    float s = 0.f;
#pragma unroll
    for (int k = 0; k < 16; k++) s += part[k * FD + col];
    out[col] = s;
}

__global__ void reduce_part16(const float* __restrict__ part, float* __restrict__ out, int n)
{
    const int i = blockIdx.x * blockDim.x + threadIdx.x;
    if (i >= n) return;
    float s = 0.f;
#pragma unroll
    for (int k = 0; k < 16; k++) s += part[(size_t)k * n + i];
    out[i] = s;
}

// ---------------- launch ----------------
extern "C" void kernel_launch(void* const* d_in, const int* in_sizes, int n_in,
                              void* d_out, int out_size)
{
    const float* h_  = (const float*)d_in[0];
    const float* E   = (const float*)d_in[1];
    const float* ob  = (const float*)d_in[2];
    const int*   lab = (const int*)  d_in[3];
    const float* Wh  = (const float*)d_in[4];
    const float* bh  = (const float*)d_in[5];
    const float* hb  = (const float*)d_in[6];
    const float* Wp  = (const float*)d_in[7];
    const float* bp  = (const float*)d_in[8];
    const float* gam = (const float*)d_in[9];
    const float* bet = (const float*)d_in[10];
    const float* sW  = (const float*)d_in[11];
    const float* sb  = (const float*)d_in[12];

    float* out    = (float*)d_out;
    float* o_loss = out;
    float* o_gWh  = out + 2048;
    float* o_ghb  = o_gWh + 512 * 1024;
    float* o_gWp  = o_ghb + 512;
    float* o_gbp  = o_gWp + 512 * 512;

    float *pv, *ppreo, *pxhat, *prstd, *pdo, *pdv, *pt, *pxf, *plog, *pm, *piz,
          *ppart, *pwt1, *pwt2, *pcs, *ppmax, *ppsum;
    __nv_bfloat16 *pEbf, *pEtbf, *pobf, *pxfbf, *pPbf;
    cudaGetSymbolAddress((void**)&pv,    g_v);
    cudaGetSymbolAddress((void**)&ppreo, g_preo);
    cudaGetSymbolAddress((void**)&pxhat, g_xhat);
    cudaGetSymbolAddress((void**)&prstd, g_rstd);
    cudaGetSymbolAddress((void**)&pdo,   g_do);
    cudaGetSymbolAddress((void**)&pdv,   g_dv);
    cudaGetSymbolAddress((void**)&pt,    g_t);
    cudaGetSymbolAddress((void**)&pxf,   g_xf);
    cudaGetSymbolAddress((void**)&plog,  g_logits);
    cudaGetSymbolAddress((void**)&pm,    g_rowm);
    cudaGetSymbolAddress((void**)&piz,   g_rowiz);
    cudaGetSymbolAddress((void**)&ppart, g_part);
    cudaGetSymbolAddress((void**)&pwt1,  g_wt1);
    cudaGetSymbolAddress((void**)&pwt2,  g_wt2);
    cudaGetSymbolAddress((void**)&pcs,   g_csum);
    cudaGetSymbolAddress((void**)&ppmax, g_pmax);
    cudaGetSymbolAddress((void**)&ppsum, g_psum);
    cudaGetSymbolAddress((void**)&pEbf,  g_Ebf);
    cudaGetSymbolAddress((void**)&pEtbf, g_Etbf);
    cudaGetSymbolAddress((void**)&pobf,  g_obf);
    cudaGetSymbolAddress((void**)&pxfbf, g_xfbf);
    cudaGetSymbolAddress((void**)&pPbf,  g_Pbf);

    cudaFuncSetAttribute((const void*)tgemm<1,1>,    cudaFuncAttributeMaxDynamicSharedMemorySize, SM_SPLIT);
    cudaFuncSetAttribute((const void*)tgemm<3,1>,    cudaFuncAttributeMaxDynamicSharedMemorySize, SM_SPLIT);
    cudaFuncSetAttribute((const void*)tgemm2<0>,     cudaFuncAttributeMaxDynamicSharedMemorySize, SM_SINGLE);
    cudaFuncSetAttribute((const void*)tgemm2<2>,     cudaFuncAttributeMaxDynamicSharedMemorySize, SM_SINGLE);
    cudaFuncSetAttribute((const void*)tgemm2b<1,1>,  cudaFuncAttributeMaxDynamicSharedMemorySize, SM_BF);
    cudaFuncSetAttribute((const void*)tgemm2b<0,0>,  cudaFuncAttributeMaxDynamicSharedMemorySize, SM_BF);
    cudaFuncSetAttribute((const void*)tgemm2b<1,2>,  cudaFuncAttributeMaxDynamicSharedMemorySize, SM_BF);

    // T0: converts + transposes
    f2bf_k<<<((size_t)VD*FD/4 + 255)/256, 256>>>(E, pEbf, (size_t)VD*FD/4);
    transpose_bf<<<dim3(FD/32, VD/32), dim3(32,8)>>>(E, pEtbf, VD, FD);
    transpose_k<<<dim3(FD/32, FD/32), dim3(32,8)>>>(Wp, pwt1, FD, FD);

    // K1: v = relu(h @ Wh^T + bh + hb)   [fp32 split-K 4: exact relu masks]
    gemm_nt_f32_part<<<dim3(FD/BN, TOK/BM, 4), 256>>>(
        h_, Wh, ppart, TOK, FD, 256, HD, HD, FD);
    reduce_v<<<(TOK*FD + 255)/256, 256>>>(ppart, bh, hb, pv);

    // K2: pre_o = v @ Wp^T + bp          [3xtf32]
    tgemm<1,1><<<dim3(FD/128, TOK/128, 1), 256, SM_SPLIT>>>(
        pv, Wp, ppreo, TOK, FD, FD, FD, FD, FD, bp, nullptr);

    // K3: LN forward (xhat fp32, o bf16)
    ln_fwd<<<TOK, 256>>>(ppreo, pxhat, pobf, prstd, gam, bet);

    // K4: logits = o @ E^T + ob   [bf16, 3-stage pipe, fused row stats]
    tgemm2b<1,1><<<dim3(VD/128, TOK/128, 1), 256, SM_BF>>>(
        pobf, pEbf, plog, TOK, VD, FD, FD, VD, FD, ob, ppmax, ppsum, NTV);

    // K5: combine partials -> rowm, rowiz
    rowstat_fin<<<TOK, 256>>>(ppmax, ppsum, NTV, pm, piz);

    // K5b: P = softmax(logits) -> bf16
    softmax_apply_bf<<<(TOK*(VD/4) + 255)/256, 256>>>(plog, pm, piz, pPbf);

    // K6: do_part = P @ Et^T   [bf16, 3-stage pipe, split-K 4]
    tgemm2b<0,0><<<dim3(FD/128, TOK/128, 4), 256, SM_BF>>>(
        pPbf, pEtbf, ppart, TOK, FD, VD, VD, FD, 8000, nullptr, nullptr, nullptr, 0);

    // K7: fused reduce_do + LN backward -> dpre_o
    ln_bwd_fused<<<TOK, 256>>>(ppart, E, lab, pxhat, prstd, gam, pdo);

    // K8: gbp
    colsum_part<<<dim3(FD/256, 16), 256>>>(pdo, pcs);
    colsum_fin<<<FD/256, 256>>>(pcs, o_gbp);

    // K9: gWp = dpre_o^T @ v   (SIMT fp32 TN split-K 16)
    gemm_tn<<<dim3(FD/BN, FD/BM, 16), 256>>>(pdo, pv, ppart, FD, FD, 128, FD, FD, FD);
    reduce_part16<<<(FD*FD + 255)/256, 256>>>(ppart, o_gWp, FD*FD);

    // T1: gWpT
    transpose_k<<<dim3(FD/32, FD/32), dim3(32,8)>>>(o_gWp, pwt2, FD, FD);

    // K10: dpre_v = (dpre_o @ Wp) * (v>0)   [3xtf32]
    tgemm<3,1><<<dim3(FD/128, TOK/128, 1), 256, SM_SPLIT>>>(
        pdo, pwt1, pdv, TOK, FD, FD, FD, FD, FD, nullptr, pv);

    // K11: gWh = dpre_v^T @ h   (SIMT fp32 TN split-K 16)
    gemm_tn<<<dim3(HD/BN, FD/BM, 16), 256>>>(pdv, h_, ppart, FD, HD, 128, FD, HD, HD);
    reduce_part16<<<(FD*HD + 255)/256, 256>>>(ppart, o_gWh, FD*HD);

    // K12: ghb
    colsum_part<<<dim3(FD/256, 16), 256>>>(pdv, pcs);
    colsum_fin<<<FD/256, 256>>>(pcs, o_ghb);

    // K13: vu = (v @ gWp) * v   [tf32 + fused elementwise mult, into g_do]
    tgemm2<2><<<dim3(FD/128, TOK/128, 1), 256, SM_SINGLE>>>(
        pv, pwt2, pdo, TOK, FD, FD, FD, FD, FD, pv);

    // K14: t = vu @ step_W^T   [tf32]
    tgemm2<0><<<dim3(FD/128, TOK/128, 1), 256, SM_SINGLE>>>(
        pdo, sW, pt, TOK, FD, FD, FD, FD, FD, nullptr);

    // K15: fast pre-LN + LN -> xf (fp32 + bf16)
    fast_ln<<<TOK, 256>>>(ppreo, pv, pt, o_gbp, sb, gam, bet, pxf, pxfbf);

    // K16: fast logits stats only  [bf16, 3-stage pipe, STAT=2]
    tgemm2b<1,2><<<dim3(VD/128, TOK/128, 1), 256, SM_BF>>>(
        pxfbf, pEbf, nullptr, TOK, VD, FD, FD, VD, FD, ob, ppmax, ppsum, NTV);

    // K17: fast loss (fused label logit + stats combine)
    fast_loss_fin<<<TOK, 256>>>(ppmax, ppsum, NTV, pxf, E, ob, lab, o_loss);
}